// round 1
// baseline (speedup 1.0000x reference)
#include <cuda_runtime.h>
#include <cstdint>
#include <cstddef>

// Problem constants (fixed for this problem instance)
static constexpr int Bc = 4;
static constexpr int Tc = 2048;
static constexpr int Cc = 2048;
static constexpr int NH = 16;
static constexpr int HD = 128;
static constexpr size_t YSZ = (size_t)Bc * Tc * Cc;   // 16777216

// Scratch (static device globals — allocation-free per harness rules)
__device__ float g_q[(size_t)Bc * Tc * Cc];
__device__ float g_y[(size_t)Bc * Tc * Cc];
__device__ float g_k[(size_t)Bc * Tc * Cc];
__device__ float g_v[(size_t)Bc * Tc * Cc];

// ---------------------------------------------------------------------------
// Tiled SGEMM: out[M,N] = A[M,K] @ Bm[N,K]^T + bias[N]
// MODE 0: QKV — scatter columns into q (scratch, head layout) / k / v outputs
// MODE 1: projection — row-major write to outY
// BM=BN=128, BK=16, 256 threads, 8x8 per-thread microtile.
// ---------------------------------------------------------------------------
template <int MODE>
__global__ __launch_bounds__(256)
void sgemm_kernel(const float* __restrict__ A, const float* __restrict__ Bm,
                  const float* __restrict__ bias,
                  float* __restrict__ outY, float* __restrict__ outQ,
                  float* __restrict__ outK, float* __restrict__ outV,
                  int M, int N, int K)
{
    constexpr int BM = 128, BN = 128, BK = 16;
    __shared__ float As[BK * BM];
    __shared__ float Bs[BK * BN];

    const int tid = threadIdx.x;
    const int tx = tid & 15;
    const int ty = tid >> 4;
    const int n0 = blockIdx.x * BN;
    const int m0 = blockIdx.y * BM;

    const float* Ab = A + (size_t)m0 * K;
    const float* Bb = Bm + (size_t)n0 * K;

    float acc[8][8];
#pragma unroll
    for (int i = 0; i < 8; i++)
#pragma unroll
        for (int j = 0; j < 8; j++) acc[i][j] = 0.0f;

    for (int k0 = 0; k0 < K; k0 += BK) {
        // Load tiles (each thread: 2 float4 per operand), store transposed.
#pragma unroll
        for (int i = 0; i < 2; i++) {
            int fl = tid + i * 256;          // 0..511 float4 slots
            int r  = fl >> 2;                // row in tile (0..127)
            int c4 = (fl & 3) << 2;          // k-offset (0,4,8,12)
            float4 av = *(const float4*)(Ab + (size_t)r * K + k0 + c4);
            float4 bv = *(const float4*)(Bb + (size_t)r * K + k0 + c4);
            As[(c4 + 0) * BM + r] = av.x;
            As[(c4 + 1) * BM + r] = av.y;
            As[(c4 + 2) * BM + r] = av.z;
            As[(c4 + 3) * BM + r] = av.w;
            Bs[(c4 + 0) * BN + r] = bv.x;
            Bs[(c4 + 1) * BN + r] = bv.y;
            Bs[(c4 + 2) * BN + r] = bv.z;
            Bs[(c4 + 3) * BN + r] = bv.w;
        }
        __syncthreads();

#pragma unroll
        for (int kk = 0; kk < BK; kk++) {
            float a[8], b[8];
            *(float4*)(a)     = *(float4*)(As + kk * BM + ty * 8);
            *(float4*)(a + 4) = *(float4*)(As + kk * BM + ty * 8 + 4);
            *(float4*)(b)     = *(float4*)(Bs + kk * BN + tx * 8);
            *(float4*)(b + 4) = *(float4*)(Bs + kk * BN + tx * 8 + 4);
#pragma unroll
            for (int i = 0; i < 8; i++)
#pragma unroll
                for (int j = 0; j < 8; j++)
                    acc[i][j] += a[i] * b[j];
        }
        __syncthreads();
    }

    // Epilogue
#pragma unroll
    for (int i = 0; i < 8; i++) {
        const int gm = m0 + ty * 8 + i;
        const int bb = gm >> 11;     // / T (2048)
        const int t  = gm & 2047;    // % T
#pragma unroll
        for (int j = 0; j < 8; j++) {
            const int gn = n0 + tx * 8 + j;
            float val = acc[i][j] + bias[gn];
            if (MODE == 0) {
                const int sec = gn >> 11;        // 0:q 1:k 2:v
                const int jj  = gn & 2047;
                const int hh  = jj >> 7;         // / HD
                const int d   = jj & 127;        // % HD
                const size_t idx = (((size_t)bb * NH + hh) * Tc + t) * HD + d;
                float* dst = (sec == 0) ? outQ : (sec == 1) ? outK : outV;
                dst[idx] = val;
            } else {
                outY[(size_t)gm * N + gn] = val;
            }
        }
    }
}

// ---------------------------------------------------------------------------
// Flash attention (causal), fp32.
// Block = one (b, h, q-tile of 64 rows). 256 threads as 16x16.
// Thread (tx,ty): S rows ty*4..+4, S cols {tx, tx+16, tx+32, tx+48};
//                 O rows ty*4..+4, O cols {tx*4..+4} U {64+tx*4..+4}.
// Shared: q_s[64][132], k_s[64][132], v_s[64][128], p_s[64][65] = 116992 B.
// ---------------------------------------------------------------------------
static constexpr int ATT_SMEM_BYTES = (64 * 132 + 64 * 132 + 64 * 128 + 64 * 65) * 4;

__global__ __launch_bounds__(256)
void attn_kernel(const float* __restrict__ Q, const float* __restrict__ K,
                 const float* __restrict__ V, float* __restrict__ Y)
{
    extern __shared__ float sm[];
    float* q_s = sm;
    float* k_s = q_s + 64 * 132;
    float* v_s = k_s + 64 * 132;
    float* p_s = v_s + 64 * 128;

    const int tid = threadIdx.x;
    const int tx = tid & 15;
    const int ty = tid >> 4;
    const int qb = blockIdx.x;
    const int h  = blockIdx.y;
    const int b  = blockIdx.z;

    const size_t bh = (((size_t)b * NH) + h) * Tc * HD;
    const float* Qb = Q + bh + (size_t)qb * 64 * HD;
    const float* Kb = K + bh;
    const float* Vb = V + bh;
    const float scale = 0.08838834764831845f;   // 1/sqrt(128)

    // Load + pre-scale Q tile (64 x 128) into stride-132 smem
#pragma unroll
    for (int i = 0; i < 8; i++) {
        int fl = tid + i * 256;        // 0..2047 float4 slots
        int r  = fl >> 5;              // row
        int c4 = (fl & 31) << 2;       // col
        float4 v4 = *(const float4*)(Qb + r * HD + c4);
        v4.x *= scale; v4.y *= scale; v4.z *= scale; v4.w *= scale;
        *(float4*)(q_s + r * 132 + c4) = v4;
    }

    float o[4][8];
    float mrow[4], lrow[4];
#pragma unroll
    for (int i = 0; i < 4; i++) {
        mrow[i] = -1e30f;
        lrow[i] = 0.0f;
#pragma unroll
        for (int c = 0; c < 8; c++) o[i][c] = 0.0f;
    }

    for (int jb = 0; jb <= qb; jb++) {
        __syncthreads();   // prev PV done (and Q visible on first iter)
        const float* Kt = Kb + (size_t)jb * 64 * HD;
        const float* Vt = Vb + (size_t)jb * 64 * HD;
#pragma unroll
        for (int i = 0; i < 8; i++) {
            int fl = tid + i * 256;
            int r  = fl >> 5;
            int c4 = (fl & 31) << 2;
            *(float4*)(k_s + r * 132 + c4) = *(const float4*)(Kt + r * HD + c4);
            *(float4*)(v_s + r * HD  + c4) = *(const float4*)(Vt + r * HD + c4);
        }
        __syncthreads();

        // S = Qs * Ks^T   (64x64 tile, 4x4 per thread)
        float s_acc[4][4];
#pragma unroll
        for (int i = 0; i < 4; i++)
#pragma unroll
            for (int j = 0; j < 4; j++) s_acc[i][j] = 0.0f;

#pragma unroll 4
        for (int d4 = 0; d4 < 32; d4++) {
            float4 qf[4], kf[4];
#pragma unroll
            for (int i = 0; i < 4; i++)
                qf[i] = *(float4*)(q_s + (ty * 4 + i) * 132 + d4 * 4);
#pragma unroll
            for (int j = 0; j < 4; j++)
                kf[j] = *(float4*)(k_s + (tx + 16 * j) * 132 + d4 * 4);
#pragma unroll
            for (int i = 0; i < 4; i++)
#pragma unroll
                for (int j = 0; j < 4; j++)
                    s_acc[i][j] += qf[i].x * kf[j].x + qf[i].y * kf[j].y +
                                   qf[i].z * kf[j].z + qf[i].w * kf[j].w;
        }

        if (jb == qb) {   // causal mask on diagonal tile
#pragma unroll
            for (int i = 0; i < 4; i++)
#pragma unroll
                for (int j = 0; j < 4; j++)
                    if (tx + 16 * j > ty * 4 + i) s_acc[i][j] = -1e30f;
        }

        // Online softmax
#pragma unroll
        for (int i = 0; i < 4; i++) {
            float tm = fmaxf(fmaxf(s_acc[i][0], s_acc[i][1]),
                             fmaxf(s_acc[i][2], s_acc[i][3]));
#pragma unroll
            for (int s = 8; s >= 1; s >>= 1)
                tm = fmaxf(tm, __shfl_xor_sync(0xffffffffu, tm, s));
            float nm = fmaxf(mrow[i], tm);
            float alpha = __expf(mrow[i] - nm);
            mrow[i] = nm;
            float p0 = __expf(s_acc[i][0] - nm);
            float p1 = __expf(s_acc[i][1] - nm);
            float p2 = __expf(s_acc[i][2] - nm);
            float p3 = __expf(s_acc[i][3] - nm);
            float rs = p0 + p1 + p2 + p3;
#pragma unroll
            for (int s = 8; s >= 1; s >>= 1)
                rs += __shfl_xor_sync(0xffffffffu, rs, s);
            lrow[i] = lrow[i] * alpha + rs;
#pragma unroll
            for (int c = 0; c < 8; c++) o[i][c] *= alpha;
            p_s[(ty * 4 + i) * 65 + tx]      = p0;
            p_s[(ty * 4 + i) * 65 + tx + 16] = p1;
            p_s[(ty * 4 + i) * 65 + tx + 32] = p2;
            p_s[(ty * 4 + i) * 65 + tx + 48] = p3;
        }
        __syncthreads();

        // O += P * V
#pragma unroll 2
        for (int j = 0; j < 64; j++) {
            float4 va = *(float4*)(v_s + j * HD + tx * 4);
            float4 vb = *(float4*)(v_s + j * HD + 64 + tx * 4);
#pragma unroll
            for (int i = 0; i < 4; i++) {
                float pv = p_s[(ty * 4 + i) * 65 + j];
                o[i][0] += pv * va.x; o[i][1] += pv * va.y;
                o[i][2] += pv * va.z; o[i][3] += pv * va.w;
                o[i][4] += pv * vb.x; o[i][5] += pv * vb.y;
                o[i][6] += pv * vb.z; o[i][7] += pv * vb.w;
            }
        }
    }

    // Normalize and write y in [B, T, C] layout (heads re-interleaved)
#pragma unroll
    for (int i = 0; i < 4; i++) {
        float inv = 1.0f / lrow[i];
        int row = qb * 64 + ty * 4 + i;
        float* yr = Y + ((size_t)(b * Tc + row)) * Cc + h * HD;
        float4 w0 = make_float4(o[i][0] * inv, o[i][1] * inv, o[i][2] * inv, o[i][3] * inv);
        float4 w1 = make_float4(o[i][4] * inv, o[i][5] * inv, o[i][6] * inv, o[i][7] * inv);
        *(float4*)(yr + tx * 4)      = w0;
        *(float4*)(yr + 64 + tx * 4) = w1;
    }
}

// ---------------------------------------------------------------------------
// Launch
// ---------------------------------------------------------------------------
extern "C" void kernel_launch(void* const* d_in, const int* in_sizes, int n_in,
                              void* d_out, int out_size)
{
    const float* x    = (const float*)d_in[0];
    const float* Wqkv = (const float*)d_in[1];
    const float* bqkv = (const float*)d_in[2];
    const float* Wout = (const float*)d_in[3];
    const float* bout = (const float*)d_in[4];
    float* out = (float*)d_out;

    float *qp, *yp, *kp, *vp;
    cudaGetSymbolAddress((void**)&qp, g_q);
    cudaGetSymbolAddress((void**)&yp, g_y);
    if ((size_t)out_size >= 3 * YSZ) {
        kp = out + YSZ;          // new_k segment of output
        vp = out + 2 * YSZ;      // new_v segment of output
    } else {
        cudaGetSymbolAddress((void**)&kp, g_k);
        cudaGetSymbolAddress((void**)&vp, g_v);
    }

    cudaFuncSetAttribute(attn_kernel,
                         cudaFuncAttributeMaxDynamicSharedMemorySize,
                         ATT_SMEM_BYTES);

    // 1) QKV projection: [8192, 6144]
    sgemm_kernel<0><<<dim3(6144 / 128, 8192 / 128), 256>>>(
        x, Wqkv, bqkv, nullptr, qp, kp, vp, Bc * Tc, 3 * Cc, Cc);

    // 2) Causal attention
    attn_kernel<<<dim3(Tc / 64, NH, Bc), 256, ATT_SMEM_BYTES>>>(qp, kp, vp, yp);

    // 3) Output projection: [8192, 2048]
    sgemm_kernel<1><<<dim3(2048 / 128, 8192 / 128), 256>>>(
        yp, Wout, bout, out, nullptr, nullptr, nullptr, Bc * Tc, Cc, Cc);
}

// round 2
// speedup vs baseline: 1.9321x; 1.9321x over previous
#include <cuda_runtime.h>
#include <cstdint>
#include <cstddef>

// Problem constants (fixed for this problem instance)
static constexpr int Bc = 4;
static constexpr int Tc = 2048;
static constexpr int Cc = 2048;
static constexpr int NH = 16;
static constexpr int HD = 128;
static constexpr size_t YSZ = (size_t)Bc * Tc * Cc;   // 16777216

// Scratch (static device globals — allocation-free per harness rules)
__device__ float g_q[(size_t)Bc * Tc * Cc];
__device__ float g_y[(size_t)Bc * Tc * Cc];
__device__ float g_k[(size_t)Bc * Tc * Cc];
__device__ float g_v[(size_t)Bc * Tc * Cc];

// ---------------------------------------------------------------------------
// TF32 tensor-core GEMM: out[M,N] = A[M,K] @ Bm[N,K]^T + bias[N]
// mma.sync.aligned.m16n8k8.row.col.f32.tf32.tf32.f32
// Block tile 128x128, BK=32, 8 warps (4 M x 2 N), warp tile 32x64.
// smem uses permuted-k layout: element k at (k&3)*8 + (k>>2) within a
// 36-float row, so each lane's fragment data for all 4 k-steps is contiguous
// (2x LDS.128 per row instead of 8x conflicted LDS.32).
// MODE 0: QKV — scatter columns into q (head layout) / k / v outputs
// MODE 1: projection — row-major write to outY
// ---------------------------------------------------------------------------
__device__ __forceinline__ uint32_t f2tf(float f) {
    uint32_t u;
    asm("cvt.rna.tf32.f32 %0, %1;" : "=r"(u) : "f"(f));
    return u;
}

#define MMA_TF32(d, a0, a1, a2, a3, b0, b1)                                   \
    asm volatile(                                                             \
        "mma.sync.aligned.m16n8k8.row.col.f32.tf32.tf32.f32 "                 \
        "{%0,%1,%2,%3}, {%4,%5,%6,%7}, {%8,%9}, {%0,%1,%2,%3};"               \
        : "+f"(d[0]), "+f"(d[1]), "+f"(d[2]), "+f"(d[3])                      \
        : "r"(a0), "r"(a1), "r"(a2), "r"(a3), "r"(b0), "r"(b1))

template <int MODE>
__global__ __launch_bounds__(256, 2)
void gemm_tf32(const float* __restrict__ A, const float* __restrict__ Bm,
               const float* __restrict__ bias,
               float* __restrict__ outY, float* __restrict__ outQ,
               float* __restrict__ outK, float* __restrict__ outV,
               int M, int N, int K)
{
    constexpr int LDSR = 36;           // floats per smem row (32 data + 4 pad)
    __shared__ uint32_t As[128 * LDSR];
    __shared__ uint32_t Bs[128 * LDSR];

    const int tid  = threadIdx.x;
    const int lane = tid & 31;
    const int warp = tid >> 5;
    const int wm   = warp & 3;          // 4 warps along M
    const int wn   = warp >> 2;         // 2 warps along N
    const int m_off = wm * 32;
    const int n_off = wn * 64;
    const int grp = lane >> 2;          // 0..7
    const int tig = lane & 3;           // 0..3

    const float* Ag = A  + (size_t)(blockIdx.y * 128) * K;
    const float* Bg = Bm + (size_t)(blockIdx.x * 128) * K;

    float acc[2][8][4];
#pragma unroll
    for (int mi = 0; mi < 2; mi++)
#pragma unroll
        for (int ni = 0; ni < 8; ni++)
#pragma unroll
            for (int r = 0; r < 4; r++) acc[mi][ni][r] = 0.0f;

    for (int k0 = 0; k0 < K; k0 += 32) {
        __syncthreads();   // previous iteration's LDS reads complete
        // Global -> smem (tf32-converted, permuted-k scatter)
#pragma unroll
        for (int i = 0; i < 4; i++) {
            int fl = tid + i * 256;      // 0..1023 float4 slots
            int rr = fl >> 3;            // row 0..127
            int cc = fl & 7;             // k/4 group 0..7
            float4 a4 = *(const float4*)(Ag + (size_t)rr * K + k0 + cc * 4);
            float4 b4 = *(const float4*)(Bg + (size_t)rr * K + k0 + cc * 4);
            uint32_t* pa = As + rr * LDSR + cc;
            pa[0]  = f2tf(a4.x); pa[8]  = f2tf(a4.y);
            pa[16] = f2tf(a4.z); pa[24] = f2tf(a4.w);
            uint32_t* pb = Bs + rr * LDSR + cc;
            pb[0]  = f2tf(b4.x); pb[8]  = f2tf(b4.y);
            pb[16] = f2tf(b4.z); pb[24] = f2tf(b4.w);
        }
        __syncthreads();

        // Compute: 2 k-step-pairs, each covering 2 mma k-steps via .xy / .zw
#pragma unroll
        for (int jp = 0; jp < 2; jp++) {
            uint4 af[2][2];
#pragma unroll
            for (int mi = 0; mi < 2; mi++) {
                int r0 = m_off + mi * 16 + grp;
                af[mi][0] = *(const uint4*)(As + r0 * LDSR + tig * 8 + jp * 4);
                af[mi][1] = *(const uint4*)(As + (r0 + 8) * LDSR + tig * 8 + jp * 4);
            }
#pragma unroll
            for (int nc = 0; nc < 2; nc++) {
                uint4 bf[4];
#pragma unroll
                for (int nj = 0; nj < 4; nj++) {
                    int col = n_off + (nc * 4 + nj) * 8 + grp;
                    bf[nj] = *(const uint4*)(Bs + col * LDSR + tig * 8 + jp * 4);
                }
#pragma unroll
                for (int mi = 0; mi < 2; mi++)
#pragma unroll
                    for (int nj = 0; nj < 4; nj++) {
                        float* d = acc[mi][nc * 4 + nj];
                        MMA_TF32(d, af[mi][0].x, af[mi][1].x, af[mi][0].y, af[mi][1].y,
                                 bf[nj].x, bf[nj].y);
                        MMA_TF32(d, af[mi][0].z, af[mi][1].z, af[mi][0].w, af[mi][1].w,
                                 bf[nj].z, bf[nj].w);
                    }
            }
        }
    }

    // Epilogue: c0,c1 -> row grp, cols 2*tig,2*tig+1 ; c2,c3 -> row grp+8
#pragma unroll
    for (int mi = 0; mi < 2; mi++) {
#pragma unroll
        for (int s = 0; s < 2; s++) {
            const int gm = blockIdx.y * 128 + m_off + mi * 16 + grp + s * 8;
            const int bb = gm >> 11;     // / T (2048)
            const int t  = gm & 2047;    // % T
#pragma unroll
            for (int ni = 0; ni < 8; ni++) {
                const int gn = blockIdx.x * 128 + n_off + ni * 8 + tig * 2;
                float v0 = acc[mi][ni][s * 2 + 0] + bias[gn];
                float v1 = acc[mi][ni][s * 2 + 1] + bias[gn + 1];
                if (MODE == 0) {
                    const int sec = gn >> 11;        // 0:q 1:k 2:v
                    const int jj  = gn & 2047;
                    const int hh  = jj >> 7;         // head
                    const int d   = jj & 127;        // dim (even)
                    const size_t idx = (((size_t)bb * NH + hh) * Tc + t) * HD + d;
                    float* dst = (sec == 0) ? outQ : (sec == 1) ? outK : outV;
                    *(float2*)(dst + idx) = make_float2(v0, v1);
                } else {
                    *(float2*)(outY + (size_t)gm * N + gn) = make_float2(v0, v1);
                }
            }
        }
    }
}

// ---------------------------------------------------------------------------
// Flash attention (causal), fp32. (unchanged from round 0)
// Block = one (b, h, q-tile of 64 rows). 256 threads as 16x16.
// ---------------------------------------------------------------------------
static constexpr int ATT_SMEM_BYTES = (64 * 132 + 64 * 132 + 64 * 128 + 64 * 65) * 4;

__global__ __launch_bounds__(256)
void attn_kernel(const float* __restrict__ Q, const float* __restrict__ K,
                 const float* __restrict__ V, float* __restrict__ Y)
{
    extern __shared__ float sm[];
    float* q_s = sm;
    float* k_s = q_s + 64 * 132;
    float* v_s = k_s + 64 * 132;
    float* p_s = v_s + 64 * 128;

    const int tid = threadIdx.x;
    const int tx = tid & 15;
    const int ty = tid >> 4;
    const int qb = blockIdx.x;
    const int h  = blockIdx.y;
    const int b  = blockIdx.z;

    const size_t bh = (((size_t)b * NH) + h) * Tc * HD;
    const float* Qb = Q + bh + (size_t)qb * 64 * HD;
    const float* Kb = K + bh;
    const float* Vb = V + bh;
    const float scale = 0.08838834764831845f;   // 1/sqrt(128)

#pragma unroll
    for (int i = 0; i < 8; i++) {
        int fl = tid + i * 256;
        int r  = fl >> 5;
        int c4 = (fl & 31) << 2;
        float4 v4 = *(const float4*)(Qb + r * HD + c4);
        v4.x *= scale; v4.y *= scale; v4.z *= scale; v4.w *= scale;
        *(float4*)(q_s + r * 132 + c4) = v4;
    }

    float o[4][8];
    float mrow[4], lrow[4];
#pragma unroll
    for (int i = 0; i < 4; i++) {
        mrow[i] = -1e30f;
        lrow[i] = 0.0f;
#pragma unroll
        for (int c = 0; c < 8; c++) o[i][c] = 0.0f;
    }

    for (int jb = 0; jb <= qb; jb++) {
        __syncthreads();
        const float* Kt = Kb + (size_t)jb * 64 * HD;
        const float* Vt = Vb + (size_t)jb * 64 * HD;
#pragma unroll
        for (int i = 0; i < 8; i++) {
            int fl = tid + i * 256;
            int r  = fl >> 5;
            int c4 = (fl & 31) << 2;
            *(float4*)(k_s + r * 132 + c4) = *(const float4*)(Kt + r * HD + c4);
            *(float4*)(v_s + r * HD  + c4) = *(const float4*)(Vt + r * HD + c4);
        }
        __syncthreads();

        float s_acc[4][4];
#pragma unroll
        for (int i = 0; i < 4; i++)
#pragma unroll
            for (int j = 0; j < 4; j++) s_acc[i][j] = 0.0f;

#pragma unroll 4
        for (int d4 = 0; d4 < 32; d4++) {
            float4 qf[4], kf[4];
#pragma unroll
            for (int i = 0; i < 4; i++)
                qf[i] = *(float4*)(q_s + (ty * 4 + i) * 132 + d4 * 4);
#pragma unroll
            for (int j = 0; j < 4; j++)
                kf[j] = *(float4*)(k_s + (tx + 16 * j) * 132 + d4 * 4);
#pragma unroll
            for (int i = 0; i < 4; i++)
#pragma unroll
                for (int j = 0; j < 4; j++)
                    s_acc[i][j] += qf[i].x * kf[j].x + qf[i].y * kf[j].y +
                                   qf[i].z * kf[j].z + qf[i].w * kf[j].w;
        }

        if (jb == qb) {
#pragma unroll
            for (int i = 0; i < 4; i++)
#pragma unroll
                for (int j = 0; j < 4; j++)
                    if (tx + 16 * j > ty * 4 + i) s_acc[i][j] = -1e30f;
        }

#pragma unroll
        for (int i = 0; i < 4; i++) {
            float tm = fmaxf(fmaxf(s_acc[i][0], s_acc[i][1]),
                             fmaxf(s_acc[i][2], s_acc[i][3]));
#pragma unroll
            for (int s = 8; s >= 1; s >>= 1)
                tm = fmaxf(tm, __shfl_xor_sync(0xffffffffu, tm, s));
            float nm = fmaxf(mrow[i], tm);
            float alpha = __expf(mrow[i] - nm);
            mrow[i] = nm;
            float p0 = __expf(s_acc[i][0] - nm);
            float p1 = __expf(s_acc[i][1] - nm);
            float p2 = __expf(s_acc[i][2] - nm);
            float p3 = __expf(s_acc[i][3] - nm);
            float rs = p0 + p1 + p2 + p3;
#pragma unroll
            for (int s = 8; s >= 1; s >>= 1)
                rs += __shfl_xor_sync(0xffffffffu, rs, s);
            lrow[i] = lrow[i] * alpha + rs;
#pragma unroll
            for (int c = 0; c < 8; c++) o[i][c] *= alpha;
            p_s[(ty * 4 + i) * 65 + tx]      = p0;
            p_s[(ty * 4 + i) * 65 + tx + 16] = p1;
            p_s[(ty * 4 + i) * 65 + tx + 32] = p2;
            p_s[(ty * 4 + i) * 65 + tx + 48] = p3;
        }
        __syncthreads();

#pragma unroll 2
        for (int j = 0; j < 64; j++) {
            float4 va = *(float4*)(v_s + j * HD + tx * 4);
            float4 vb = *(float4*)(v_s + j * HD + 64 + tx * 4);
#pragma unroll
            for (int i = 0; i < 4; i++) {
                float pv = p_s[(ty * 4 + i) * 65 + j];
                o[i][0] += pv * va.x; o[i][1] += pv * va.y;
                o[i][2] += pv * va.z; o[i][3] += pv * va.w;
                o[i][4] += pv * vb.x; o[i][5] += pv * vb.y;
                o[i][6] += pv * vb.z; o[i][7] += pv * vb.w;
            }
        }
    }

#pragma unroll
    for (int i = 0; i < 4; i++) {
        float inv = 1.0f / lrow[i];
        int row = qb * 64 + ty * 4 + i;
        float* yr = Y + ((size_t)(b * Tc + row)) * Cc + h * HD;
        float4 w0 = make_float4(o[i][0] * inv, o[i][1] * inv, o[i][2] * inv, o[i][3] * inv);
        float4 w1 = make_float4(o[i][4] * inv, o[i][5] * inv, o[i][6] * inv, o[i][7] * inv);
        *(float4*)(yr + tx * 4)      = w0;
        *(float4*)(yr + 64 + tx * 4) = w1;
    }
}

// ---------------------------------------------------------------------------
// Launch
// ---------------------------------------------------------------------------
extern "C" void kernel_launch(void* const* d_in, const int* in_sizes, int n_in,
                              void* d_out, int out_size)
{
    const float* x    = (const float*)d_in[0];
    const float* Wqkv = (const float*)d_in[1];
    const float* bqkv = (const float*)d_in[2];
    const float* Wout = (const float*)d_in[3];
    const float* bout = (const float*)d_in[4];
    float* out = (float*)d_out;

    float *qp, *yp, *kp, *vp;
    cudaGetSymbolAddress((void**)&qp, g_q);
    cudaGetSymbolAddress((void**)&yp, g_y);
    if ((size_t)out_size >= 3 * YSZ) {
        kp = out + YSZ;          // new_k segment of output
        vp = out + 2 * YSZ;      // new_v segment of output
    } else {
        cudaGetSymbolAddress((void**)&kp, g_k);
        cudaGetSymbolAddress((void**)&vp, g_v);
    }

    cudaFuncSetAttribute(attn_kernel,
                         cudaFuncAttributeMaxDynamicSharedMemorySize,
                         ATT_SMEM_BYTES);

    // 1) QKV projection: [8192, 6144] = x @ Wqkv^T + bqkv   (tf32 tensor cores)
    gemm_tf32<0><<<dim3(6144 / 128, 8192 / 128), 256>>>(
        x, Wqkv, bqkv, nullptr, qp, kp, vp, Bc * Tc, 3 * Cc, Cc);

    // 2) Causal attention (fp32 flash)
    attn_kernel<<<dim3(Tc / 64, NH, Bc), 256, ATT_SMEM_BYTES>>>(qp, kp, vp, yp);

    // 3) Output projection: [8192, 2048]   (tf32 tensor cores)
    gemm_tf32<1><<<dim3(2048 / 128, 8192 / 128), 256>>>(
        yp, Wout, bout, out, nullptr, nullptr, nullptr, Bc * Tc, Cc, Cc);
}

// round 4
// speedup vs baseline: 2.8390x; 1.4694x over previous
#include <cuda_runtime.h>
#include <cstdint>
#include <cstddef>

// Problem constants (fixed for this problem instance)
static constexpr int Bc = 4;
static constexpr int Tc = 2048;
static constexpr int Cc = 2048;
static constexpr int NH = 16;
static constexpr int HD = 128;
static constexpr size_t YSZ = (size_t)Bc * Tc * Cc;   // 16777216

// Scratch (static device globals — allocation-free per harness rules)
__device__ float g_q[(size_t)Bc * Tc * Cc];
__device__ float g_y[(size_t)Bc * Tc * Cc];
__device__ float g_k[(size_t)Bc * Tc * Cc];
__device__ float g_v[(size_t)Bc * Tc * Cc];

__device__ __forceinline__ uint32_t f2tf(float f) {
    uint32_t u;
    asm("cvt.rna.tf32.f32 %0, %1;" : "=r"(u) : "f"(f));
    return u;
}

#define MMA_TF32(d, a0, a1, a2, a3, b0, b1)                                   \
    asm volatile(                                                             \
        "mma.sync.aligned.m16n8k8.row.col.f32.tf32.tf32.f32 "                 \
        "{%0,%1,%2,%3}, {%4,%5,%6,%7}, {%8,%9}, {%0,%1,%2,%3};"               \
        : "+f"(d[0]), "+f"(d[1]), "+f"(d[2]), "+f"(d[3])                      \
        : "r"(a0), "r"(a1), "r"(a2), "r"(a3), "r"(b0), "r"(b1))

// ---------------------------------------------------------------------------
// TF32 tensor-core GEMM: out[M,N] = A[M,K] @ Bm[N,K]^T + bias[N]   (unchanged)
// ---------------------------------------------------------------------------
template <int MODE>
__global__ __launch_bounds__(256, 2)
void gemm_tf32(const float* __restrict__ A, const float* __restrict__ Bm,
               const float* __restrict__ bias,
               float* __restrict__ outY, float* __restrict__ outQ,
               float* __restrict__ outK, float* __restrict__ outV,
               int M, int N, int K)
{
    constexpr int LDSR = 36;
    __shared__ uint32_t As[128 * LDSR];
    __shared__ uint32_t Bs[128 * LDSR];

    const int tid  = threadIdx.x;
    const int lane = tid & 31;
    const int warp = tid >> 5;
    const int wm   = warp & 3;
    const int wn   = warp >> 2;
    const int m_off = wm * 32;
    const int n_off = wn * 64;
    const int grp = lane >> 2;
    const int tig = lane & 3;

    const float* Ag = A  + (size_t)(blockIdx.y * 128) * K;
    const float* Bg = Bm + (size_t)(blockIdx.x * 128) * K;

    float acc[2][8][4];
#pragma unroll
    for (int mi = 0; mi < 2; mi++)
#pragma unroll
        for (int ni = 0; ni < 8; ni++)
#pragma unroll
            for (int r = 0; r < 4; r++) acc[mi][ni][r] = 0.0f;

    for (int k0 = 0; k0 < K; k0 += 32) {
        __syncthreads();
#pragma unroll
        for (int i = 0; i < 4; i++) {
            int fl = tid + i * 256;
            int rr = fl >> 3;
            int cc = fl & 7;
            float4 a4 = *(const float4*)(Ag + (size_t)rr * K + k0 + cc * 4);
            float4 b4 = *(const float4*)(Bg + (size_t)rr * K + k0 + cc * 4);
            uint32_t* pa = As + rr * LDSR + cc;
            pa[0]  = f2tf(a4.x); pa[8]  = f2tf(a4.y);
            pa[16] = f2tf(a4.z); pa[24] = f2tf(a4.w);
            uint32_t* pb = Bs + rr * LDSR + cc;
            pb[0]  = f2tf(b4.x); pb[8]  = f2tf(b4.y);
            pb[16] = f2tf(b4.z); pb[24] = f2tf(b4.w);
        }
        __syncthreads();

#pragma unroll
        for (int jp = 0; jp < 2; jp++) {
            uint4 af[2][2];
#pragma unroll
            for (int mi = 0; mi < 2; mi++) {
                int r0 = m_off + mi * 16 + grp;
                af[mi][0] = *(const uint4*)(As + r0 * LDSR + tig * 8 + jp * 4);
                af[mi][1] = *(const uint4*)(As + (r0 + 8) * LDSR + tig * 8 + jp * 4);
            }
#pragma unroll
            for (int nc = 0; nc < 2; nc++) {
                uint4 bf[4];
#pragma unroll
                for (int nj = 0; nj < 4; nj++) {
                    int col = n_off + (nc * 4 + nj) * 8 + grp;
                    bf[nj] = *(const uint4*)(Bs + col * LDSR + tig * 8 + jp * 4);
                }
#pragma unroll
                for (int mi = 0; mi < 2; mi++)
#pragma unroll
                    for (int nj = 0; nj < 4; nj++) {
                        float* d = acc[mi][nc * 4 + nj];
                        MMA_TF32(d, af[mi][0].x, af[mi][1].x, af[mi][0].y, af[mi][1].y,
                                 bf[nj].x, bf[nj].y);
                        MMA_TF32(d, af[mi][0].z, af[mi][1].z, af[mi][0].w, af[mi][1].w,
                                 bf[nj].z, bf[nj].w);
                    }
            }
        }
    }

#pragma unroll
    for (int mi = 0; mi < 2; mi++) {
#pragma unroll
        for (int s = 0; s < 2; s++) {
            const int gm = blockIdx.y * 128 + m_off + mi * 16 + grp + s * 8;
            const int bb = gm >> 11;
            const int t  = gm & 2047;
#pragma unroll
            for (int ni = 0; ni < 8; ni++) {
                const int gn = blockIdx.x * 128 + n_off + ni * 8 + tig * 2;
                float v0 = acc[mi][ni][s * 2 + 0] + bias[gn];
                float v1 = acc[mi][ni][s * 2 + 1] + bias[gn + 1];
                if (MODE == 0) {
                    const int sec = gn >> 11;
                    const int jj  = gn & 2047;
                    const int hh  = jj >> 7;
                    const int d   = jj & 127;
                    const size_t idx = (((size_t)bb * NH + hh) * Tc + t) * HD + d;
                    float* dst = (sec == 0) ? outQ : (sec == 1) ? outK : outV;
                    *(float2*)(dst + idx) = make_float2(v0, v1);
                } else {
                    *(float2*)(outY + (size_t)gm * N + gn) = make_float2(v0, v1);
                }
            }
        }
    }
}

// ---------------------------------------------------------------------------
// Tensor-core flash attention (causal), tf32 MMA.
// Block: 128 Q rows x (h, b). 256 threads = 8 warps; warp w owns S/O rows
// [16w, 16w+16). K/V tiles of 64 rows streamed.
// smem layouts (u32, chunk-major permuted-k; pos(k) = (k&3)*8 + (k>>2)):
//   q_s : [4][128][36] (+8 pad/chunk)  tf32, pre-scaled
//   k_s : [4][64][36]  (+8)            tf32
//   vt_s: [2][128][36] (+8)            tf32, V TRANSPOSED (n-major)
//   p_s : [128][68] f32                P round-trip for PV A-fragments
// ---------------------------------------------------------------------------
static constexpr int QCH = 128 * 36 + 8;   // q/vt chunk stride (u32)
static constexpr int KCH = 64 * 36 + 8;    // k chunk stride
static constexpr int Q_WORDS  = 4 * QCH;   // 18464
static constexpr int K_WORDS  = 4 * KCH;   // 9248
static constexpr int VT_WORDS = 2 * QCH;   // 9232
static constexpr int P_WORDS  = 128 * 68;  // 8704
static constexpr int ATT_SMEM_BYTES = (Q_WORDS + K_WORDS + VT_WORDS + P_WORDS) * 4;

__global__ __launch_bounds__(256)
void attn_kernel(const float* __restrict__ Q, const float* __restrict__ K,
                 const float* __restrict__ V, float* __restrict__ Y)
{
    extern __shared__ uint32_t smu[];
    uint32_t* q_s  = smu;
    uint32_t* k_s  = q_s + Q_WORDS;
    uint32_t* vt_s = k_s + K_WORDS;
    float*    p_s  = (float*)(vt_s + VT_WORDS);

    const int tid  = threadIdx.x;
    const int lane = tid & 31;
    const int w    = tid >> 5;
    const int grp  = lane >> 2;
    const int tig  = lane & 3;
    const int qb   = (int)gridDim.x - 1 - (int)blockIdx.x;  // heavy blocks first
    const int h    = blockIdx.y;
    const int b    = blockIdx.z;

    const size_t bh = (((size_t)b * NH) + h) * Tc * HD;
    const float* Qb = Q + bh + (size_t)qb * 128 * HD;
    const float* Kb = K + bh;
    const float* Vb = V + bh;
    const float scale = 0.08838834764831845f;   // 1/sqrt(128)

    // Load + scale + convert Q tile (128 x 128) into permuted tf32 smem
#pragma unroll
    for (int i = 0; i < 16; i++) {
        int fl = tid + i * 256;
        int row = fl >> 5;
        int c4  = (fl & 31) << 2;
        float4 v4 = *(const float4*)(Qb + row * HD + c4);
        uint32_t* p = q_s + (c4 >> 5) * QCH + row * 36 + ((c4 & 31) >> 2);
        p[0]  = f2tf(v4.x * scale);
        p[8]  = f2tf(v4.y * scale);
        p[16] = f2tf(v4.z * scale);
        p[24] = f2tf(v4.w * scale);
    }

    float o[16][4];
#pragma unroll
    for (int nt = 0; nt < 16; nt++)
#pragma unroll
        for (int r = 0; r < 4; r++) o[nt][r] = 0.0f;
    float m0 = -1e30f, m1 = -1e30f, l0 = 0.0f, l1 = 0.0f;

    const int r0g = qb * 128 + 16 * w + grp;     // global q rows of this lane
    const int r1g = r0g + 8;
    const int pr0 = (16 * w + grp) * 68;         // p_s row bases
    const int pr1 = (16 * w + grp + 8) * 68;
    const int njt = 2 * qb + 2;                  // j tiles

    for (int jb = 0; jb < njt; jb++) {
        __syncthreads();   // prev PV done with k_s/vt_s (and q_s ready, 1st iter)
        const float* Kt = Kb + (size_t)jb * 64 * HD;
        const float* Vt = Vb + (size_t)jb * 64 * HD;
        // K tile -> permuted tf32
#pragma unroll
        for (int i = 0; i < 8; i++) {
            int fl = tid + i * 256;
            int row = fl >> 5;
            int c4  = (fl & 31) << 2;
            float4 v4 = *(const float4*)(Kt + row * HD + c4);
            uint32_t* p = k_s + (c4 >> 5) * KCH + row * 36 + ((c4 & 31) >> 2);
            p[0]  = f2tf(v4.x);
            p[8]  = f2tf(v4.y);
            p[16] = f2tf(v4.z);
            p[24] = f2tf(v4.w);
        }
        // V tile -> TRANSPOSED permuted tf32: vt_s[chunk][n][pos(k)]
#pragma unroll
        for (int i = 0; i < 8; i++) {
            int fl = tid + i * 256;
            int kr = fl >> 5;              // k row 0..63
            int c4 = (fl & 31) << 2;       // n base
            float4 v4 = *(const float4*)(Vt + kr * HD + c4);
            int kk = kr & 31;
            uint32_t* p = vt_s + (kr >> 5) * QCH + c4 * 36 + (kk & 3) * 8 + (kk >> 2);
            p[0]   = f2tf(v4.x);
            p[36]  = f2tf(v4.y);
            p[72]  = f2tf(v4.z);
            p[108] = f2tf(v4.w);
        }
        __syncthreads();

        // ---- S = Q * K^T  (warp: 16 x 64) ----
        float sacc[8][4];
#pragma unroll
        for (int nt = 0; nt < 8; nt++)
#pragma unroll
            for (int r = 0; r < 4; r++) sacc[nt][r] = 0.0f;

#pragma unroll
        for (int c = 0; c < 4; c++) {
#pragma unroll
            for (int jp = 0; jp < 2; jp++) {
                const uint32_t* qc = q_s + c * QCH + tig * 8 + jp * 4;
                uint4 a0 = *(const uint4*)(qc + (16 * w + grp) * 36);
                uint4 a1 = *(const uint4*)(qc + (16 * w + 8 + grp) * 36);
                const uint32_t* kc = k_s + c * KCH + tig * 8 + jp * 4;
#pragma unroll
                for (int nt = 0; nt < 8; nt++) {
                    uint4 bf = *(const uint4*)(kc + (nt * 8 + grp) * 36);
                    float* d = sacc[nt];
                    MMA_TF32(d, a0.x, a1.x, a0.y, a1.y, bf.x, bf.y);
                    MMA_TF32(d, a0.z, a1.z, a0.w, a1.w, bf.z, bf.w);
                }
            }
        }

        // ---- causal mask ----
        if (jb * 64 + 63 > qb * 128 + 16 * w) {
#pragma unroll
            for (int nt = 0; nt < 8; nt++) {
                int col = jb * 64 + nt * 8 + 2 * tig;
                if (col     > r0g) sacc[nt][0] = -1e30f;
                if (col + 1 > r0g) sacc[nt][1] = -1e30f;
                if (col     > r1g) sacc[nt][2] = -1e30f;
                if (col + 1 > r1g) sacc[nt][3] = -1e30f;
            }
        }

        // ---- online softmax (warp-local; rows live in quads) ----
        float tm0 = -1e30f, tm1 = -1e30f;
#pragma unroll
        for (int nt = 0; nt < 8; nt++) {
            tm0 = fmaxf(tm0, fmaxf(sacc[nt][0], sacc[nt][1]));
            tm1 = fmaxf(tm1, fmaxf(sacc[nt][2], sacc[nt][3]));
        }
        tm0 = fmaxf(tm0, __shfl_xor_sync(0xffffffffu, tm0, 1));
        tm0 = fmaxf(tm0, __shfl_xor_sync(0xffffffffu, tm0, 2));
        tm1 = fmaxf(tm1, __shfl_xor_sync(0xffffffffu, tm1, 1));
        tm1 = fmaxf(tm1, __shfl_xor_sync(0xffffffffu, tm1, 2));
        float nm0 = fmaxf(m0, tm0), nm1 = fmaxf(m1, tm1);
        float al0 = __expf(m0 - nm0), al1 = __expf(m1 - nm1);
        m0 = nm0; m1 = nm1;

        float sum0 = 0.0f, sum1 = 0.0f;
#pragma unroll
        for (int nt = 0; nt < 8; nt++) {
            float p0 = __expf(sacc[nt][0] - m0);
            float p1 = __expf(sacc[nt][1] - m0);
            float p2 = __expf(sacc[nt][2] - m1);
            float p3 = __expf(sacc[nt][3] - m1);
            sum0 += p0 + p1;
            sum1 += p2 + p3;
            int cc = nt * 8 + 2 * tig;
            *(float2*)(p_s + pr0 + cc) = make_float2(p0, p1);
            *(float2*)(p_s + pr1 + cc) = make_float2(p2, p3);
        }
        sum0 += __shfl_xor_sync(0xffffffffu, sum0, 1);
        sum0 += __shfl_xor_sync(0xffffffffu, sum0, 2);
        sum1 += __shfl_xor_sync(0xffffffffu, sum1, 1);
        sum1 += __shfl_xor_sync(0xffffffffu, sum1, 2);
        l0 = l0 * al0 + sum0;
        l1 = l1 * al1 + sum1;

#pragma unroll
        for (int nt = 0; nt < 16; nt++) {
            o[nt][0] *= al0; o[nt][1] *= al0;
            o[nt][2] *= al1; o[nt][3] *= al1;
        }
        __syncwarp();

        // ---- O += P * V   (warp: 16 x 128, k = 64) ----
#pragma unroll
        for (int c = 0; c < 2; c++) {
#pragma unroll
            for (int jp = 0; jp < 2; jp++) {
                const int k0a = c * 32 + jp * 16;
                uint32_t ax0 = f2tf(p_s[pr0 + k0a + tig]);
                uint32_t ax1 = f2tf(p_s[pr1 + k0a + tig]);
                uint32_t ax2 = f2tf(p_s[pr0 + k0a + tig + 4]);
                uint32_t ax3 = f2tf(p_s[pr1 + k0a + tig + 4]);
                uint32_t az0 = f2tf(p_s[pr0 + k0a + 8 + tig]);
                uint32_t az1 = f2tf(p_s[pr1 + k0a + 8 + tig]);
                uint32_t az2 = f2tf(p_s[pr0 + k0a + 8 + tig + 4]);
                uint32_t az3 = f2tf(p_s[pr1 + k0a + 8 + tig + 4]);
                const uint32_t* vc = vt_s + c * QCH + tig * 8 + jp * 4;
#pragma unroll
                for (int nt = 0; nt < 16; nt++) {
                    uint4 bf = *(const uint4*)(vc + (nt * 8 + grp) * 36);
                    float* d = o[nt];
                    MMA_TF32(d, ax0, ax1, ax2, ax3, bf.x, bf.y);
                    MMA_TF32(d, az0, az1, az2, az3, bf.z, bf.w);
                }
            }
        }
    }

    // ---- normalize + write y in [B, T, C] layout ----
    const float inv0 = 1.0f / l0;
    const float inv1 = 1.0f / l1;
    float* y0 = Y + ((size_t)(b * Tc + r0g)) * Cc + h * HD;
    float* y1 = Y + ((size_t)(b * Tc + r1g)) * Cc + h * HD;
#pragma unroll
    for (int nt = 0; nt < 16; nt++) {
        int col = nt * 8 + 2 * tig;
        *(float2*)(y0 + col) = make_float2(o[nt][0] * inv0, o[nt][1] * inv0);
        *(float2*)(y1 + col) = make_float2(o[nt][2] * inv1, o[nt][3] * inv1);
    }
}

// ---------------------------------------------------------------------------
// Launch
// ---------------------------------------------------------------------------
extern "C" void kernel_launch(void* const* d_in, const int* in_sizes, int n_in,
                              void* d_out, int out_size)
{
    const float* x    = (const float*)d_in[0];
    const float* Wqkv = (const float*)d_in[1];
    const float* bqkv = (const float*)d_in[2];
    const float* Wout = (const float*)d_in[3];
    const float* bout = (const float*)d_in[4];
    float* out = (float*)d_out;

    float *qp, *yp, *kp, *vp;
    cudaGetSymbolAddress((void**)&qp, g_q);
    cudaGetSymbolAddress((void**)&yp, g_y);
    if ((size_t)out_size >= 3 * YSZ) {
        kp = out + YSZ;          // new_k segment of output
        vp = out + 2 * YSZ;      // new_v segment of output
    } else {
        cudaGetSymbolAddress((void**)&kp, g_k);
        cudaGetSymbolAddress((void**)&vp, g_v);
    }

    cudaFuncSetAttribute(attn_kernel,
                         cudaFuncAttributeMaxDynamicSharedMemorySize,
                         ATT_SMEM_BYTES);

    // 1) QKV projection: [8192, 6144] = x @ Wqkv^T + bqkv   (tf32 tensor cores)
    gemm_tf32<0><<<dim3(6144 / 128, 8192 / 128), 256>>>(
        x, Wqkv, bqkv, nullptr, qp, kp, vp, Bc * Tc, 3 * Cc, Cc);

    // 2) Causal attention (tf32 tensor cores)
    attn_kernel<<<dim3(Tc / 128, NH, Bc), 256, ATT_SMEM_BYTES>>>(qp, kp, vp, yp);

    // 3) Output projection: [8192, 2048]   (tf32 tensor cores)
    gemm_tf32<1><<<dim3(2048 / 128, 8192 / 128), 256>>>(
        yp, Wout, bout, out, nullptr, nullptr, nullptr, Bc * Tc, Cc, Cc);
}

// round 5
// speedup vs baseline: 3.1197x; 1.0989x over previous
#include <cuda_runtime.h>
#include <cstdint>
#include <cstddef>

// Problem constants (fixed for this problem instance)
static constexpr int Bc = 4;
static constexpr int Tc = 2048;
static constexpr int Cc = 2048;
static constexpr int NH = 16;
static constexpr int HD = 128;
static constexpr size_t YSZ = (size_t)Bc * Tc * Cc;   // 16777216

// Permuted-tile geometry: [mtile][ktile][128 rows][36 words]
// word pos within row for k in [0,32): pos(k) = (k&3)*8 + (k>>2); words 32..35 pad.
static constexpr int TW   = 128 * 36;        // words per tile = 4608
static constexpr int KT64 = 64;              // K=2048 -> 64 k-tiles (all matrices)

// Scratch (static device globals — allocation-free per harness rules)
__device__ float    g_q   [(size_t)Bc * Tc * Cc];
__device__ float    g_k   [(size_t)Bc * Tc * Cc];   // fallback only
__device__ float    g_v   [(size_t)Bc * Tc * Cc];   // fallback only
__device__ uint32_t g_xp  [(size_t)(8192 / 128) * KT64 * TW];  // x  permuted
__device__ uint32_t g_wqp [(size_t)(6144 / 128) * KT64 * TW];  // Wqkv permuted
__device__ uint32_t g_wop [(size_t)(2048 / 128) * KT64 * TW];  // Wout permuted
__device__ uint32_t g_ypp [(size_t)(8192 / 128) * KT64 * TW];  // y permuted (from attn)

__device__ __forceinline__ uint32_t f2tf(float f) {
    uint32_t u;
    asm("cvt.rna.tf32.f32 %0, %1;" : "=r"(u) : "f"(f));
    return u;
}

__device__ __forceinline__ void cp16(uint32_t smem_dst, const void* gmem_src) {
    asm volatile("cp.async.cg.shared.global [%0], [%1], 16;\n"
                 :: "r"(smem_dst), "l"(gmem_src));
}
#define CP_COMMIT()  asm volatile("cp.async.commit_group;\n")
#define CP_WAIT(n)   asm volatile("cp.async.wait_group %0;\n" :: "n"(n))

#define MMA_TF32(d, a0, a1, a2, a3, b0, b1)                                   \
    asm volatile(                                                             \
        "mma.sync.aligned.m16n8k8.row.col.f32.tf32.tf32.f32 "                 \
        "{%0,%1,%2,%3}, {%4,%5,%6,%7}, {%8,%9}, {%0,%1,%2,%3};"               \
        : "+f"(d[0]), "+f"(d[1]), "+f"(d[2]), "+f"(d[3])                      \
        : "r"(a0), "r"(a1), "r"(a2), "r"(a3), "r"(b0), "r"(b1))

// ---------------------------------------------------------------------------
// Pre-pass: convert fp32 [rows x 2048] row-major -> permuted tf32 tile image.
// One thread per float4. grid = rows*2 blocks of 256.
// ---------------------------------------------------------------------------
__global__ __launch_bounds__(256)
void conv_perm(const float* __restrict__ src, uint32_t* __restrict__ dst)
{
    const int idx = blockIdx.x * 256 + threadIdx.x;   // float4 index
    const int e = idx << 2;                           // element index
    const int r = e >> 11;                            // row  (K = 2048)
    const int k = e & 2047;                           // col
    float4 v = *(const float4*)(src + ((size_t)idx << 2));
    const int rt = r >> 7, rr = r & 127;
    const int kt = k >> 5, kk = k & 31;
    uint32_t* p = dst + ((size_t)(rt * KT64 + kt) * 128 + rr) * 36
                      + ((kk & 3) << 3) + (kk >> 2);
    p[0]  = f2tf(v.x);
    p[8]  = f2tf(v.y);
    p[16] = f2tf(v.z);
    p[24] = f2tf(v.w);
}

// ---------------------------------------------------------------------------
// TF32 tensor-core GEMM on pre-permuted operands, cp.async double-buffered.
// out[M,N] = A[M,K] @ Bm[N,K]^T + bias[N], K = 2048 (64 k-tiles).
// Block tile 128x128, 8 warps (4 M x 2 N), warp tile 32x64.
// Dynamic smem: As[2][4608] ++ Bs[2][4608] u32 = 73728 B.
// MODE 0: QKV — scatter into q (head layout) / k / v.  MODE 1: row-major outY.
// ---------------------------------------------------------------------------
static constexpr int GEMM_SMEM_BYTES = 4 * TW * 4;   // 73728

template <int MODE>
__global__ __launch_bounds__(256, 2)
void gemm_pp(const uint32_t* __restrict__ Ap, const uint32_t* __restrict__ Bp,
             const float* __restrict__ bias,
             float* __restrict__ outY, float* __restrict__ outQ,
             float* __restrict__ outK, float* __restrict__ outV, int N)
{
    extern __shared__ uint32_t dyn[];
    uint32_t* As = dyn;               // [2][4608]
    uint32_t* Bs = dyn + 2 * TW;      // [2][4608]

    const int tid  = threadIdx.x;
    const int lane = tid & 31;
    const int warp = tid >> 5;
    const int wm   = warp & 3;
    const int wn   = warp >> 2;
    const int m_off = wm * 32;
    const int n_off = wn * 64;
    const int grp = lane >> 2;
    const int tig = lane & 3;

    const uint32_t* At = Ap + (size_t)blockIdx.y * KT64 * TW;
    const uint32_t* Bt = Bp + (size_t)blockIdx.x * KT64 * TW;

    uint32_t sA, sB;
    {
        uint64_t a = __cvta_generic_to_shared(As);
        uint64_t b = __cvta_generic_to_shared(Bs);
        sA = (uint32_t)a; sB = (uint32_t)b;
    }

    // issue one k-tile's cp.async copies into buffer `buf`
    auto issue = [&](int kt, int buf) {
        const uint32_t* ga = At + (size_t)kt * TW;
        const uint32_t* gb = Bt + (size_t)kt * TW;
        const uint32_t dA = sA + buf * (TW * 4);
        const uint32_t dB = sB + buf * (TW * 4);
#pragma unroll
        for (int i = 0; i < 9; i++) {
            int c = tid + i * 256;
            if (i < 4) {
                cp16(dA + c * 16, ga + c * 4);
            } else if (i == 4) {
                if (c < 1152) cp16(dA + c * 16, ga + c * 4);
                else          cp16(dB + (c - 1152) * 16, gb + (c - 1152) * 4);
            } else {
                cp16(dB + (c - 1152) * 16, gb + (c - 1152) * 4);
            }
        }
    };

    float acc[2][8][4];
#pragma unroll
    for (int mi = 0; mi < 2; mi++)
#pragma unroll
        for (int ni = 0; ni < 8; ni++)
#pragma unroll
            for (int r = 0; r < 4; r++) acc[mi][ni][r] = 0.0f;

    issue(0, 0);
    CP_COMMIT();

    for (int kt = 0; kt < KT64; kt++) {
        if (kt + 1 < KT64) {
            issue(kt + 1, (kt + 1) & 1);
            CP_COMMIT();
            CP_WAIT(1);
        } else {
            CP_WAIT(0);
        }
        __syncthreads();

        const uint32_t* Ab = As + (kt & 1) * TW;
        const uint32_t* Bb = Bs + (kt & 1) * TW;
#pragma unroll
        for (int jp = 0; jp < 2; jp++) {
            uint4 af[2][2];
#pragma unroll
            for (int mi = 0; mi < 2; mi++) {
                int r0 = m_off + mi * 16 + grp;
                af[mi][0] = *(const uint4*)(Ab + r0 * 36 + tig * 8 + jp * 4);
                af[mi][1] = *(const uint4*)(Ab + (r0 + 8) * 36 + tig * 8 + jp * 4);
            }
#pragma unroll
            for (int nc = 0; nc < 2; nc++) {
                uint4 bf[4];
#pragma unroll
                for (int nj = 0; nj < 4; nj++) {
                    int col = n_off + (nc * 4 + nj) * 8 + grp;
                    bf[nj] = *(const uint4*)(Bb + col * 36 + tig * 8 + jp * 4);
                }
#pragma unroll
                for (int mi = 0; mi < 2; mi++)
#pragma unroll
                    for (int nj = 0; nj < 4; nj++) {
                        float* d = acc[mi][nc * 4 + nj];
                        MMA_TF32(d, af[mi][0].x, af[mi][1].x, af[mi][0].y, af[mi][1].y,
                                 bf[nj].x, bf[nj].y);
                        MMA_TF32(d, af[mi][0].z, af[mi][1].z, af[mi][0].w, af[mi][1].w,
                                 bf[nj].z, bf[nj].w);
                    }
            }
        }
        __syncthreads();
    }

    // Epilogue
#pragma unroll
    for (int mi = 0; mi < 2; mi++) {
#pragma unroll
        for (int s = 0; s < 2; s++) {
            const int gm = blockIdx.y * 128 + m_off + mi * 16 + grp + s * 8;
            const int bb = gm >> 11;
            const int t  = gm & 2047;
#pragma unroll
            for (int ni = 0; ni < 8; ni++) {
                const int gn = blockIdx.x * 128 + n_off + ni * 8 + tig * 2;
                float v0 = acc[mi][ni][s * 2 + 0] + bias[gn];
                float v1 = acc[mi][ni][s * 2 + 1] + bias[gn + 1];
                if (MODE == 0) {
                    const int sec = gn >> 11;
                    const int jj  = gn & 2047;
                    const int hh  = jj >> 7;
                    const int d   = jj & 127;
                    const size_t idx = (((size_t)bb * NH + hh) * Tc + t) * HD + d;
                    float* dst = (sec == 0) ? outQ : (sec == 1) ? outK : outV;
                    *(float2*)(dst + idx) = make_float2(v0, v1);
                } else {
                    *(float2*)(outY + (size_t)gm * N + gn) = make_float2(v0, v1);
                }
            }
        }
    }
}

// ---------------------------------------------------------------------------
// Tensor-core flash attention (causal), tf32 MMA.  (compute unchanged from R4)
// Epilogue now writes y DIRECTLY in the permuted-tf32 tile image (g_ypp),
// ready for gemm_pp<1>'s cp.async consumption.
// ---------------------------------------------------------------------------
static constexpr int QCH = 128 * 36 + 8;
static constexpr int KCH = 64 * 36 + 8;
static constexpr int Q_WORDS  = 4 * QCH;
static constexpr int K_WORDS  = 4 * KCH;
static constexpr int VT_WORDS = 2 * QCH;
static constexpr int P_WORDS  = 128 * 68;
static constexpr int ATT_SMEM_BYTES = (Q_WORDS + K_WORDS + VT_WORDS + P_WORDS) * 4;

__global__ __launch_bounds__(256)
void attn_kernel(const float* __restrict__ Q, const float* __restrict__ K,
                 const float* __restrict__ V, uint32_t* __restrict__ Yp)
{
    extern __shared__ uint32_t smu[];
    uint32_t* q_s  = smu;
    uint32_t* k_s  = q_s + Q_WORDS;
    uint32_t* vt_s = k_s + K_WORDS;
    float*    p_s  = (float*)(vt_s + VT_WORDS);

    const int tid  = threadIdx.x;
    const int lane = tid & 31;
    const int w    = tid >> 5;
    const int grp  = lane >> 2;
    const int tig  = lane & 3;
    const int qb   = (int)gridDim.x - 1 - (int)blockIdx.x;
    const int h    = blockIdx.y;
    const int b    = blockIdx.z;

    const size_t bh = (((size_t)b * NH) + h) * Tc * HD;
    const float* Qb = Q + bh + (size_t)qb * 128 * HD;
    const float* Kb = K + bh;
    const float* Vb = V + bh;
    const float scale = 0.08838834764831845f;   // 1/sqrt(128)

#pragma unroll
    for (int i = 0; i < 16; i++) {
        int fl = tid + i * 256;
        int row = fl >> 5;
        int c4  = (fl & 31) << 2;
        float4 v4 = *(const float4*)(Qb + row * HD + c4);
        uint32_t* p = q_s + (c4 >> 5) * QCH + row * 36 + ((c4 & 31) >> 2);
        p[0]  = f2tf(v4.x * scale);
        p[8]  = f2tf(v4.y * scale);
        p[16] = f2tf(v4.z * scale);
        p[24] = f2tf(v4.w * scale);
    }

    float o[16][4];
#pragma unroll
    for (int nt = 0; nt < 16; nt++)
#pragma unroll
        for (int r = 0; r < 4; r++) o[nt][r] = 0.0f;
    float m0 = -1e30f, m1 = -1e30f, l0 = 0.0f, l1 = 0.0f;

    const int r0g = qb * 128 + 16 * w + grp;
    const int r1g = r0g + 8;
    const int pr0 = (16 * w + grp) * 68;
    const int pr1 = (16 * w + grp + 8) * 68;
    const int njt = 2 * qb + 2;

    for (int jb = 0; jb < njt; jb++) {
        __syncthreads();
        const float* Kt = Kb + (size_t)jb * 64 * HD;
        const float* Vt = Vb + (size_t)jb * 64 * HD;
#pragma unroll
        for (int i = 0; i < 8; i++) {
            int fl = tid + i * 256;
            int row = fl >> 5;
            int c4  = (fl & 31) << 2;
            float4 v4 = *(const float4*)(Kt + row * HD + c4);
            uint32_t* p = k_s + (c4 >> 5) * KCH + row * 36 + ((c4 & 31) >> 2);
            p[0]  = f2tf(v4.x);
            p[8]  = f2tf(v4.y);
            p[16] = f2tf(v4.z);
            p[24] = f2tf(v4.w);
        }
#pragma unroll
        for (int i = 0; i < 8; i++) {
            int fl = tid + i * 256;
            int kr = fl >> 5;
            int c4 = (fl & 31) << 2;
            float4 v4 = *(const float4*)(Vt + kr * HD + c4);
            int kk = kr & 31;
            uint32_t* p = vt_s + (kr >> 5) * QCH + c4 * 36 + (kk & 3) * 8 + (kk >> 2);
            p[0]   = f2tf(v4.x);
            p[36]  = f2tf(v4.y);
            p[72]  = f2tf(v4.z);
            p[108] = f2tf(v4.w);
        }
        __syncthreads();

        float sacc[8][4];
#pragma unroll
        for (int nt = 0; nt < 8; nt++)
#pragma unroll
            for (int r = 0; r < 4; r++) sacc[nt][r] = 0.0f;

#pragma unroll
        for (int c = 0; c < 4; c++) {
#pragma unroll
            for (int jp = 0; jp < 2; jp++) {
                const uint32_t* qc = q_s + c * QCH + tig * 8 + jp * 4;
                uint4 a0 = *(const uint4*)(qc + (16 * w + grp) * 36);
                uint4 a1 = *(const uint4*)(qc + (16 * w + 8 + grp) * 36);
                const uint32_t* kc = k_s + c * KCH + tig * 8 + jp * 4;
#pragma unroll
                for (int nt = 0; nt < 8; nt++) {
                    uint4 bf = *(const uint4*)(kc + (nt * 8 + grp) * 36);
                    float* d = sacc[nt];
                    MMA_TF32(d, a0.x, a1.x, a0.y, a1.y, bf.x, bf.y);
                    MMA_TF32(d, a0.z, a1.z, a0.w, a1.w, bf.z, bf.w);
                }
            }
        }

        if (jb * 64 + 63 > qb * 128 + 16 * w) {
#pragma unroll
            for (int nt = 0; nt < 8; nt++) {
                int col = jb * 64 + nt * 8 + 2 * tig;
                if (col     > r0g) sacc[nt][0] = -1e30f;
                if (col + 1 > r0g) sacc[nt][1] = -1e30f;
                if (col     > r1g) sacc[nt][2] = -1e30f;
                if (col + 1 > r1g) sacc[nt][3] = -1e30f;
            }
        }

        float tm0 = -1e30f, tm1 = -1e30f;
#pragma unroll
        for (int nt = 0; nt < 8; nt++) {
            tm0 = fmaxf(tm0, fmaxf(sacc[nt][0], sacc[nt][1]));
            tm1 = fmaxf(tm1, fmaxf(sacc[nt][2], sacc[nt][3]));
        }
        tm0 = fmaxf(tm0, __shfl_xor_sync(0xffffffffu, tm0, 1));
        tm0 = fmaxf(tm0, __shfl_xor_sync(0xffffffffu, tm0, 2));
        tm1 = fmaxf(tm1, __shfl_xor_sync(0xffffffffu, tm1, 1));
        tm1 = fmaxf(tm1, __shfl_xor_sync(0xffffffffu, tm1, 2));
        float nm0 = fmaxf(m0, tm0), nm1 = fmaxf(m1, tm1);
        float al0 = __expf(m0 - nm0), al1 = __expf(m1 - nm1);
        m0 = nm0; m1 = nm1;

        float sum0 = 0.0f, sum1 = 0.0f;
#pragma unroll
        for (int nt = 0; nt < 8; nt++) {
            float p0 = __expf(sacc[nt][0] - m0);
            float p1 = __expf(sacc[nt][1] - m0);
            float p2 = __expf(sacc[nt][2] - m1);
            float p3 = __expf(sacc[nt][3] - m1);
            sum0 += p0 + p1;
            sum1 += p2 + p3;
            int cc = nt * 8 + 2 * tig;
            *(float2*)(p_s + pr0 + cc) = make_float2(p0, p1);
            *(float2*)(p_s + pr1 + cc) = make_float2(p2, p3);
        }
        sum0 += __shfl_xor_sync(0xffffffffu, sum0, 1);
        sum0 += __shfl_xor_sync(0xffffffffu, sum0, 2);
        sum1 += __shfl_xor_sync(0xffffffffu, sum1, 1);
        sum1 += __shfl_xor_sync(0xffffffffu, sum1, 2);
        l0 = l0 * al0 + sum0;
        l1 = l1 * al1 + sum1;

#pragma unroll
        for (int nt = 0; nt < 16; nt++) {
            o[nt][0] *= al0; o[nt][1] *= al0;
            o[nt][2] *= al1; o[nt][3] *= al1;
        }
        __syncwarp();

#pragma unroll
        for (int c = 0; c < 2; c++) {
#pragma unroll
            for (int jp = 0; jp < 2; jp++) {
                const int k0a = c * 32 + jp * 16;
                uint32_t ax0 = f2tf(p_s[pr0 + k0a + tig]);
                uint32_t ax1 = f2tf(p_s[pr1 + k0a + tig]);
                uint32_t ax2 = f2tf(p_s[pr0 + k0a + tig + 4]);
                uint32_t ax3 = f2tf(p_s[pr1 + k0a + tig + 4]);
                uint32_t az0 = f2tf(p_s[pr0 + k0a + 8 + tig]);
                uint32_t az1 = f2tf(p_s[pr1 + k0a + 8 + tig]);
                uint32_t az2 = f2tf(p_s[pr0 + k0a + 8 + tig + 4]);
                uint32_t az3 = f2tf(p_s[pr1 + k0a + 8 + tig + 4]);
                const uint32_t* vc = vt_s + c * QCH + tig * 8 + jp * 4;
#pragma unroll
                for (int nt = 0; nt < 16; nt++) {
                    uint4 bf = *(const uint4*)(vc + (nt * 8 + grp) * 36);
                    float* d = o[nt];
                    MMA_TF32(d, ax0, ax1, ax2, ax3, bf.x, bf.y);
                    MMA_TF32(d, az0, az1, az2, az3, bf.z, bf.w);
                }
            }
        }
    }

    // ---- normalize + write y straight into permuted tf32 image ----
    const float inv0 = 1.0f / l0;
    const float inv1 = 1.0f / l1;
    const int mt  = b * (Tc / 128) + qb;
    const int rr0 = 16 * w + grp;
    const int rr1 = rr0 + 8;
#pragma unroll
    for (int nt = 0; nt < 16; nt++) {
        const int colh = nt * 8 + 2 * tig;        // even, 0..126 within head
        const int gn   = h * HD + colh;
        const int kt   = gn >> 5;
        const int kk   = gn & 31;
        const int pos  = ((kk & 3) << 3) + (kk >> 2);
        uint32_t* baseT = Yp + (size_t)(mt * KT64 + kt) * TW;
        baseT[rr0 * 36 + pos]     = f2tf(o[nt][0] * inv0);
        baseT[rr0 * 36 + pos + 8] = f2tf(o[nt][1] * inv0);
        baseT[rr1 * 36 + pos]     = f2tf(o[nt][2] * inv1);
        baseT[rr1 * 36 + pos + 8] = f2tf(o[nt][3] * inv1);
    }
}

// ---------------------------------------------------------------------------
// Launch
// ---------------------------------------------------------------------------
extern "C" void kernel_launch(void* const* d_in, const int* in_sizes, int n_in,
                              void* d_out, int out_size)
{
    const float* x    = (const float*)d_in[0];
    const float* Wqkv = (const float*)d_in[1];
    const float* bqkv = (const float*)d_in[2];
    const float* Wout = (const float*)d_in[3];
    const float* bout = (const float*)d_in[4];
    float* out = (float*)d_out;

    float *qp, *kp, *vp;
    uint32_t *xpp, *wqp, *wop, *ypp;
    cudaGetSymbolAddress((void**)&qp,  g_q);
    cudaGetSymbolAddress((void**)&xpp, g_xp);
    cudaGetSymbolAddress((void**)&wqp, g_wqp);
    cudaGetSymbolAddress((void**)&wop, g_wop);
    cudaGetSymbolAddress((void**)&ypp, g_ypp);
    if ((size_t)out_size >= 3 * YSZ) {
        kp = out + YSZ;          // new_k segment of output
        vp = out + 2 * YSZ;      // new_v segment of output
    } else {
        cudaGetSymbolAddress((void**)&kp, g_k);
        cudaGetSymbolAddress((void**)&vp, g_v);
    }

    cudaFuncSetAttribute(attn_kernel,
                         cudaFuncAttributeMaxDynamicSharedMemorySize,
                         ATT_SMEM_BYTES);
    cudaFuncSetAttribute(gemm_pp<0>,
                         cudaFuncAttributeMaxDynamicSharedMemorySize,
                         GEMM_SMEM_BYTES);
    cudaFuncSetAttribute(gemm_pp<1>,
                         cudaFuncAttributeMaxDynamicSharedMemorySize,
                         GEMM_SMEM_BYTES);

    // 0) Pre-permute x, Wqkv, Wout into tf32 tile images (DRAM-bound, ~40us)
    conv_perm<<<8192 * 2, 256>>>(x,    xpp);
    conv_perm<<<6144 * 2, 256>>>(Wqkv, wqp);
    conv_perm<<<2048 * 2, 256>>>(Wout, wop);

    // 1) QKV projection: [8192, 6144] = x @ Wqkv^T + bqkv  (cp.async + tf32 MMA)
    gemm_pp<0><<<dim3(6144 / 128, 8192 / 128), 256, GEMM_SMEM_BYTES>>>(
        xpp, wqp, bqkv, nullptr, qp, kp, vp, 3 * Cc);

    // 2) Causal attention (tf32 tensor cores); writes y permuted into g_ypp
    attn_kernel<<<dim3(Tc / 128, NH, Bc), 256, ATT_SMEM_BYTES>>>(qp, kp, vp, ypp);

    // 3) Output projection: [8192, 2048] = y @ Wout^T + bout
    gemm_pp<1><<<dim3(2048 / 128, 8192 / 128), 256, GEMM_SMEM_BYTES>>>(
        ypp, wop, bout, out, nullptr, nullptr, nullptr, Cc);
}

// round 6
// speedup vs baseline: 3.2127x; 1.0298x over previous
#include <cuda_runtime.h>
#include <cstdint>
#include <cstddef>

// Problem constants (fixed for this problem instance)
static constexpr int Bc = 4;
static constexpr int Tc = 2048;
static constexpr int Cc = 2048;
static constexpr int NH = 16;
static constexpr int HD = 128;
static constexpr size_t YSZ = (size_t)Bc * Tc * Cc;   // 16777216

// Permuted-tile geometry: [mtile][ktile][128 rows][36 words]
// word pos within row for k in [0,32): pos(k) = (k&3)*8 + (k>>2); words 32..35 pad.
static constexpr int TW   = 128 * 36;        // words per tile = 4608
static constexpr int KT64 = 64;              // K=2048 -> 64 k-tiles (all matrices)

// Scratch (static device globals — allocation-free per harness rules)
__device__ float    g_q   [(size_t)Bc * Tc * Cc];
__device__ float    g_k   [(size_t)Bc * Tc * Cc];   // fallback only
__device__ float    g_v   [(size_t)Bc * Tc * Cc];   // fallback only
__device__ uint32_t g_xp  [(size_t)(8192 / 128) * KT64 * TW];  // x  permuted
__device__ uint32_t g_wqp [(size_t)(6144 / 128) * KT64 * TW];  // Wqkv permuted
__device__ uint32_t g_wop [(size_t)(2048 / 128) * KT64 * TW];  // Wout permuted
__device__ uint32_t g_ypp [(size_t)(8192 / 128) * KT64 * TW];  // y permuted (from attn)

__device__ __forceinline__ uint32_t f2tf(float f) {
    uint32_t u;
    asm("cvt.rna.tf32.f32 %0, %1;" : "=r"(u) : "f"(f));
    return u;
}

__device__ __forceinline__ void cp16(uint32_t smem_dst, const void* gmem_src) {
    asm volatile("cp.async.cg.shared.global [%0], [%1], 16;\n"
                 :: "r"(smem_dst), "l"(gmem_src));
}
#define CP_COMMIT()  asm volatile("cp.async.commit_group;\n")
#define CP_WAIT(n)   asm volatile("cp.async.wait_group %0;\n" :: "n"(n))

#define MMA_TF32(d, a0, a1, a2, a3, b0, b1)                                   \
    asm volatile(                                                             \
        "mma.sync.aligned.m16n8k8.row.col.f32.tf32.tf32.f32 "                 \
        "{%0,%1,%2,%3}, {%4,%5,%6,%7}, {%8,%9}, {%0,%1,%2,%3};"               \
        : "+f"(d[0]), "+f"(d[1]), "+f"(d[2]), "+f"(d[3])                      \
        : "r"(a0), "r"(a1), "r"(a2), "r"(a3), "r"(b0), "r"(b1))

// ---------------------------------------------------------------------------
// Pre-pass: convert fp32 [rows x 2048] row-major -> permuted tf32 tile image.
// ---------------------------------------------------------------------------
__global__ __launch_bounds__(256)
void conv_perm(const float* __restrict__ src, uint32_t* __restrict__ dst)
{
    const int idx = blockIdx.x * 256 + threadIdx.x;   // float4 index
    const int e = idx << 2;
    const int r = e >> 11;
    const int k = e & 2047;
    float4 v = *(const float4*)(src + ((size_t)idx << 2));
    const int rt = r >> 7, rr = r & 127;
    const int kt = k >> 5, kk = k & 31;
    uint32_t* p = dst + ((size_t)(rt * KT64 + kt) * 128 + rr) * 36
                      + ((kk & 3) << 3) + (kk >> 2);
    p[0]  = f2tf(v.x);
    p[8]  = f2tf(v.y);
    p[16] = f2tf(v.z);
    p[24] = f2tf(v.w);
}

// ---------------------------------------------------------------------------
// TF32 tensor-core GEMM on pre-permuted operands, 3-stage cp.async pipeline.
// out[M,N] = A[M,K] @ Bm[N,K]^T + bias[N], K = 2048 (64 k-tiles).
// Block tile 128x128, 4 warps (2x2), warp tile 64x64.
// Dynamic smem: As[3][4608] ++ Bs[3][4608] u32 = 110592 B (2 CTAs/SM).
// Per warp per k-tile: 32 LDS.128 feed 128 MMAs.
// ---------------------------------------------------------------------------
static constexpr int GEMM_SMEM_BYTES = 6 * TW * 4;   // 110592

template <int MODE>
__global__ __launch_bounds__(128, 2)
void gemm_pp(const uint32_t* __restrict__ Ap, const uint32_t* __restrict__ Bp,
             const float* __restrict__ bias,
             float* __restrict__ outY, float* __restrict__ outQ,
             float* __restrict__ outK, float* __restrict__ outV, int N)
{
    extern __shared__ uint32_t dyn[];
    uint32_t* As = dyn;               // [3][4608]
    uint32_t* Bs = dyn + 3 * TW;      // [3][4608]

    const int tid  = threadIdx.x;
    const int lane = tid & 31;
    const int warp = tid >> 5;        // 0..3
    const int wm   = warp >> 1;       // 2 warps along M
    const int wn   = warp & 1;        // 2 warps along N
    const int m_off = wm * 64;
    const int n_off = wn * 64;
    const int grp = lane >> 2;
    const int tig = lane & 3;

    const uint32_t* At = Ap + (size_t)blockIdx.y * KT64 * TW;
    const uint32_t* Bt = Bp + (size_t)blockIdx.x * KT64 * TW;

    uint32_t sA, sB;
    {
        uint64_t a = __cvta_generic_to_shared(As);
        uint64_t b = __cvta_generic_to_shared(Bs);
        sA = (uint32_t)a; sB = (uint32_t)b;
    }

    // issue one k-tile's cp.async copies into stage `buf` (18 x 16B per thread)
    auto issue = [&](int kt, int buf) {
        const uint32_t* ga = At + (size_t)kt * TW;
        const uint32_t* gb = Bt + (size_t)kt * TW;
        const uint32_t dA = sA + buf * (TW * 4);
        const uint32_t dB = sB + buf * (TW * 4);
#pragma unroll
        for (int i = 0; i < 18; i++) {
            int c = tid + i * 128;
            if (i < 9) cp16(dA + c * 16, ga + c * 4);
            else       cp16(dB + (c - 1152) * 16, gb + (c - 1152) * 4);
        }
    };

    float acc[4][8][4];
#pragma unroll
    for (int mi = 0; mi < 4; mi++)
#pragma unroll
        for (int ni = 0; ni < 8; ni++)
#pragma unroll
            for (int r = 0; r < 4; r++) acc[mi][ni][r] = 0.0f;

    issue(0, 0); CP_COMMIT();
    issue(1, 1); CP_COMMIT();

    for (int kt = 0; kt < KT64; kt++) {
        if (kt + 2 < KT64) issue(kt + 2, (kt + 2) % 3);
        CP_COMMIT();           // (possibly empty group; keeps wait count uniform)
        CP_WAIT(2);            // stage kt complete
        __syncthreads();

        const uint32_t* Ab = As + (kt % 3) * TW;
        const uint32_t* Bb = Bs + (kt % 3) * TW;
#pragma unroll
        for (int jp = 0; jp < 2; jp++) {
            uint4 af[4][2];
#pragma unroll
            for (int mi = 0; mi < 4; mi++) {
                int r0 = m_off + mi * 16 + grp;
                af[mi][0] = *(const uint4*)(Ab + r0 * 36 + tig * 8 + jp * 4);
                af[mi][1] = *(const uint4*)(Ab + (r0 + 8) * 36 + tig * 8 + jp * 4);
            }
#pragma unroll
            for (int nc = 0; nc < 2; nc++) {
                uint4 bf[4];
#pragma unroll
                for (int nj = 0; nj < 4; nj++) {
                    int col = n_off + (nc * 4 + nj) * 8 + grp;
                    bf[nj] = *(const uint4*)(Bb + col * 36 + tig * 8 + jp * 4);
                }
#pragma unroll
                for (int mi = 0; mi < 4; mi++)
#pragma unroll
                    for (int nj = 0; nj < 4; nj++) {
                        float* d = acc[mi][nc * 4 + nj];
                        MMA_TF32(d, af[mi][0].x, af[mi][1].x, af[mi][0].y, af[mi][1].y,
                                 bf[nj].x, bf[nj].y);
                        MMA_TF32(d, af[mi][0].z, af[mi][1].z, af[mi][0].w, af[mi][1].w,
                                 bf[nj].z, bf[nj].w);
                    }
            }
        }
        __syncthreads();       // all warps done with stage before it is re-filled
    }

    // Epilogue
#pragma unroll
    for (int mi = 0; mi < 4; mi++) {
#pragma unroll
        for (int s = 0; s < 2; s++) {
            const int gm = blockIdx.y * 128 + m_off + mi * 16 + grp + s * 8;
            const int bb = gm >> 11;
            const int t  = gm & 2047;
#pragma unroll
            for (int ni = 0; ni < 8; ni++) {
                const int gn = blockIdx.x * 128 + n_off + ni * 8 + tig * 2;
                float v0 = acc[mi][ni][s * 2 + 0] + bias[gn];
                float v1 = acc[mi][ni][s * 2 + 1] + bias[gn + 1];
                if (MODE == 0) {
                    const int sec = gn >> 11;
                    const int jj  = gn & 2047;
                    const int hh  = jj >> 7;
                    const int d   = jj & 127;
                    const size_t idx = (((size_t)bb * NH + hh) * Tc + t) * HD + d;
                    float* dst = (sec == 0) ? outQ : (sec == 1) ? outK : outV;
                    *(float2*)(dst + idx) = make_float2(v0, v1);
                } else {
                    *(float2*)(outY + (size_t)gm * N + gn) = make_float2(v0, v1);
                }
            }
        }
    }
}

// ---------------------------------------------------------------------------
// Tensor-core flash attention (causal), tf32 MMA. (unchanged from R5)
// ---------------------------------------------------------------------------
static constexpr int QCH = 128 * 36 + 8;
static constexpr int KCH = 64 * 36 + 8;
static constexpr int Q_WORDS  = 4 * QCH;
static constexpr int K_WORDS  = 4 * KCH;
static constexpr int VT_WORDS = 2 * QCH;
static constexpr int P_WORDS  = 128 * 68;
static constexpr int ATT_SMEM_BYTES = (Q_WORDS + K_WORDS + VT_WORDS + P_WORDS) * 4;

__global__ __launch_bounds__(256)
void attn_kernel(const float* __restrict__ Q, const float* __restrict__ K,
                 const float* __restrict__ V, uint32_t* __restrict__ Yp)
{
    extern __shared__ uint32_t smu[];
    uint32_t* q_s  = smu;
    uint32_t* k_s  = q_s + Q_WORDS;
    uint32_t* vt_s = k_s + K_WORDS;
    float*    p_s  = (float*)(vt_s + VT_WORDS);

    const int tid  = threadIdx.x;
    const int lane = tid & 31;
    const int w    = tid >> 5;
    const int grp  = lane >> 2;
    const int tig  = lane & 3;
    const int qb   = (int)gridDim.x - 1 - (int)blockIdx.x;
    const int h    = blockIdx.y;
    const int b    = blockIdx.z;

    const size_t bh = (((size_t)b * NH) + h) * Tc * HD;
    const float* Qb = Q + bh + (size_t)qb * 128 * HD;
    const float* Kb = K + bh;
    const float* Vb = V + bh;
    const float scale = 0.08838834764831845f;   // 1/sqrt(128)

#pragma unroll
    for (int i = 0; i < 16; i++) {
        int fl = tid + i * 256;
        int row = fl >> 5;
        int c4  = (fl & 31) << 2;
        float4 v4 = *(const float4*)(Qb + row * HD + c4);
        uint32_t* p = q_s + (c4 >> 5) * QCH + row * 36 + ((c4 & 31) >> 2);
        p[0]  = f2tf(v4.x * scale);
        p[8]  = f2tf(v4.y * scale);
        p[16] = f2tf(v4.z * scale);
        p[24] = f2tf(v4.w * scale);
    }

    float o[16][4];
#pragma unroll
    for (int nt = 0; nt < 16; nt++)
#pragma unroll
        for (int r = 0; r < 4; r++) o[nt][r] = 0.0f;
    float m0 = -1e30f, m1 = -1e30f, l0 = 0.0f, l1 = 0.0f;

    const int r0g = qb * 128 + 16 * w + grp;
    const int r1g = r0g + 8;
    const int pr0 = (16 * w + grp) * 68;
    const int pr1 = (16 * w + grp + 8) * 68;
    const int njt = 2 * qb + 2;

    for (int jb = 0; jb < njt; jb++) {
        __syncthreads();
        const float* Kt = Kb + (size_t)jb * 64 * HD;
        const float* Vt = Vb + (size_t)jb * 64 * HD;
#pragma unroll
        for (int i = 0; i < 8; i++) {
            int fl = tid + i * 256;
            int row = fl >> 5;
            int c4  = (fl & 31) << 2;
            float4 v4 = *(const float4*)(Kt + row * HD + c4);
            uint32_t* p = k_s + (c4 >> 5) * KCH + row * 36 + ((c4 & 31) >> 2);
            p[0]  = f2tf(v4.x);
            p[8]  = f2tf(v4.y);
            p[16] = f2tf(v4.z);
            p[24] = f2tf(v4.w);
        }
#pragma unroll
        for (int i = 0; i < 8; i++) {
            int fl = tid + i * 256;
            int kr = fl >> 5;
            int c4 = (fl & 31) << 2;
            float4 v4 = *(const float4*)(Vt + kr * HD + c4);
            int kk = kr & 31;
            uint32_t* p = vt_s + (kr >> 5) * QCH + c4 * 36 + (kk & 3) * 8 + (kk >> 2);
            p[0]   = f2tf(v4.x);
            p[36]  = f2tf(v4.y);
            p[72]  = f2tf(v4.z);
            p[108] = f2tf(v4.w);
        }
        __syncthreads();

        float sacc[8][4];
#pragma unroll
        for (int nt = 0; nt < 8; nt++)
#pragma unroll
            for (int r = 0; r < 4; r++) sacc[nt][r] = 0.0f;

#pragma unroll
        for (int c = 0; c < 4; c++) {
#pragma unroll
            for (int jp = 0; jp < 2; jp++) {
                const uint32_t* qc = q_s + c * QCH + tig * 8 + jp * 4;
                uint4 a0 = *(const uint4*)(qc + (16 * w + grp) * 36);
                uint4 a1 = *(const uint4*)(qc + (16 * w + 8 + grp) * 36);
                const uint32_t* kc = k_s + c * KCH + tig * 8 + jp * 4;
#pragma unroll
                for (int nt = 0; nt < 8; nt++) {
                    uint4 bf = *(const uint4*)(kc + (nt * 8 + grp) * 36);
                    float* d = sacc[nt];
                    MMA_TF32(d, a0.x, a1.x, a0.y, a1.y, bf.x, bf.y);
                    MMA_TF32(d, a0.z, a1.z, a0.w, a1.w, bf.z, bf.w);
                }
            }
        }

        if (jb * 64 + 63 > qb * 128 + 16 * w) {
#pragma unroll
            for (int nt = 0; nt < 8; nt++) {
                int col = jb * 64 + nt * 8 + 2 * tig;
                if (col     > r0g) sacc[nt][0] = -1e30f;
                if (col + 1 > r0g) sacc[nt][1] = -1e30f;
                if (col     > r1g) sacc[nt][2] = -1e30f;
                if (col + 1 > r1g) sacc[nt][3] = -1e30f;
            }
        }

        float tm0 = -1e30f, tm1 = -1e30f;
#pragma unroll
        for (int nt = 0; nt < 8; nt++) {
            tm0 = fmaxf(tm0, fmaxf(sacc[nt][0], sacc[nt][1]));
            tm1 = fmaxf(tm1, fmaxf(sacc[nt][2], sacc[nt][3]));
        }
        tm0 = fmaxf(tm0, __shfl_xor_sync(0xffffffffu, tm0, 1));
        tm0 = fmaxf(tm0, __shfl_xor_sync(0xffffffffu, tm0, 2));
        tm1 = fmaxf(tm1, __shfl_xor_sync(0xffffffffu, tm1, 1));
        tm1 = fmaxf(tm1, __shfl_xor_sync(0xffffffffu, tm1, 2));
        float nm0 = fmaxf(m0, tm0), nm1 = fmaxf(m1, tm1);
        float al0 = __expf(m0 - nm0), al1 = __expf(m1 - nm1);
        m0 = nm0; m1 = nm1;

        float sum0 = 0.0f, sum1 = 0.0f;
#pragma unroll
        for (int nt = 0; nt < 8; nt++) {
            float p0 = __expf(sacc[nt][0] - m0);
            float p1 = __expf(sacc[nt][1] - m0);
            float p2 = __expf(sacc[nt][2] - m1);
            float p3 = __expf(sacc[nt][3] - m1);
            sum0 += p0 + p1;
            sum1 += p2 + p3;
            int cc = nt * 8 + 2 * tig;
            *(float2*)(p_s + pr0 + cc) = make_float2(p0, p1);
            *(float2*)(p_s + pr1 + cc) = make_float2(p2, p3);
        }
        sum0 += __shfl_xor_sync(0xffffffffu, sum0, 1);
        sum0 += __shfl_xor_sync(0xffffffffu, sum0, 2);
        sum1 += __shfl_xor_sync(0xffffffffu, sum1, 1);
        sum1 += __shfl_xor_sync(0xffffffffu, sum1, 2);
        l0 = l0 * al0 + sum0;
        l1 = l1 * al1 + sum1;

#pragma unroll
        for (int nt = 0; nt < 16; nt++) {
            o[nt][0] *= al0; o[nt][1] *= al0;
            o[nt][2] *= al1; o[nt][3] *= al1;
        }
        __syncwarp();

#pragma unroll
        for (int c = 0; c < 2; c++) {
#pragma unroll
            for (int jp = 0; jp < 2; jp++) {
                const int k0a = c * 32 + jp * 16;
                uint32_t ax0 = f2tf(p_s[pr0 + k0a + tig]);
                uint32_t ax1 = f2tf(p_s[pr1 + k0a + tig]);
                uint32_t ax2 = f2tf(p_s[pr0 + k0a + tig + 4]);
                uint32_t ax3 = f2tf(p_s[pr1 + k0a + tig + 4]);
                uint32_t az0 = f2tf(p_s[pr0 + k0a + 8 + tig]);
                uint32_t az1 = f2tf(p_s[pr1 + k0a + 8 + tig]);
                uint32_t az2 = f2tf(p_s[pr0 + k0a + 8 + tig + 4]);
                uint32_t az3 = f2tf(p_s[pr1 + k0a + 8 + tig + 4]);
                const uint32_t* vc = vt_s + c * QCH + tig * 8 + jp * 4;
#pragma unroll
                for (int nt = 0; nt < 16; nt++) {
                    uint4 bf = *(const uint4*)(vc + (nt * 8 + grp) * 36);
                    float* d = o[nt];
                    MMA_TF32(d, ax0, ax1, ax2, ax3, bf.x, bf.y);
                    MMA_TF32(d, az0, az1, az2, az3, bf.z, bf.w);
                }
            }
        }
    }

    // ---- normalize + write y straight into permuted tf32 image ----
    const float inv0 = 1.0f / l0;
    const float inv1 = 1.0f / l1;
    const int mt  = b * (Tc / 128) + qb;
    const int rr0 = 16 * w + grp;
    const int rr1 = rr0 + 8;
#pragma unroll
    for (int nt = 0; nt < 16; nt++) {
        const int colh = nt * 8 + 2 * tig;
        const int gn   = h * HD + colh;
        const int kt   = gn >> 5;
        const int kk   = gn & 31;
        const int pos  = ((kk & 3) << 3) + (kk >> 2);
        uint32_t* baseT = Yp + (size_t)(mt * KT64 + kt) * TW;
        baseT[rr0 * 36 + pos]     = f2tf(o[nt][0] * inv0);
        baseT[rr0 * 36 + pos + 8] = f2tf(o[nt][1] * inv0);
        baseT[rr1 * 36 + pos]     = f2tf(o[nt][2] * inv1);
        baseT[rr1 * 36 + pos + 8] = f2tf(o[nt][3] * inv1);
    }
}

// ---------------------------------------------------------------------------
// Launch
// ---------------------------------------------------------------------------
extern "C" void kernel_launch(void* const* d_in, const int* in_sizes, int n_in,
                              void* d_out, int out_size)
{
    const float* x    = (const float*)d_in[0];
    const float* Wqkv = (const float*)d_in[1];
    const float* bqkv = (const float*)d_in[2];
    const float* Wout = (const float*)d_in[3];
    const float* bout = (const float*)d_in[4];
    float* out = (float*)d_out;

    float *qp, *kp, *vp;
    uint32_t *xpp, *wqp, *wop, *ypp;
    cudaGetSymbolAddress((void**)&qp,  g_q);
    cudaGetSymbolAddress((void**)&xpp, g_xp);
    cudaGetSymbolAddress((void**)&wqp, g_wqp);
    cudaGetSymbolAddress((void**)&wop, g_wop);
    cudaGetSymbolAddress((void**)&ypp, g_ypp);
    if ((size_t)out_size >= 3 * YSZ) {
        kp = out + YSZ;          // new_k segment of output
        vp = out + 2 * YSZ;      // new_v segment of output
    } else {
        cudaGetSymbolAddress((void**)&kp, g_k);
        cudaGetSymbolAddress((void**)&vp, g_v);
    }

    cudaFuncSetAttribute(attn_kernel,
                         cudaFuncAttributeMaxDynamicSharedMemorySize,
                         ATT_SMEM_BYTES);
    cudaFuncSetAttribute(gemm_pp<0>,
                         cudaFuncAttributeMaxDynamicSharedMemorySize,
                         GEMM_SMEM_BYTES);
    cudaFuncSetAttribute(gemm_pp<1>,
                         cudaFuncAttributeMaxDynamicSharedMemorySize,
                         GEMM_SMEM_BYTES);

    // 0) Pre-permute x, Wqkv, Wout into tf32 tile images (DRAM-bound)
    conv_perm<<<8192 * 2, 256>>>(x,    xpp);
    conv_perm<<<6144 * 2, 256>>>(Wqkv, wqp);
    conv_perm<<<2048 * 2, 256>>>(Wout, wop);

    // 1) QKV projection: [8192, 6144] = x @ Wqkv^T + bqkv
    gemm_pp<0><<<dim3(6144 / 128, 8192 / 128), 128, GEMM_SMEM_BYTES>>>(
        xpp, wqp, bqkv, nullptr, qp, kp, vp, 3 * Cc);

    // 2) Causal attention (tf32 tensor cores); writes y permuted into g_ypp
    attn_kernel<<<dim3(Tc / 128, NH, Bc), 256, ATT_SMEM_BYTES>>>(qp, kp, vp, ypp);

    // 3) Output projection: [8192, 2048] = y @ Wout^T + bout
    gemm_pp<1><<<dim3(2048 / 128, 8192 / 128), 128, GEMM_SMEM_BYTES>>>(
        ypp, wop, bout, out, nullptr, nullptr, nullptr, Cc);
}

// round 11
// speedup vs baseline: 3.5248x; 1.0971x over previous
#include <cuda_runtime.h>
#include <cstdint>
#include <cstddef>

// Problem constants (fixed for this problem instance)
static constexpr int Bc = 4;
static constexpr int Tc = 2048;
static constexpr int Cc = 2048;
static constexpr int NH = 16;
static constexpr int HD = 128;
static constexpr size_t YSZ = (size_t)Bc * Tc * Cc;   // 16777216

// Permuted-tile geometry: [mtile][ktile][128 rows][36 words]
// word pos within row for k in [0,32): pos(k) = (k&3)*8 + (k>>2); words 32..35 pad.
static constexpr int TW   = 128 * 36;        // words per tile = 4608
static constexpr int KT64 = 64;              // K=2048 -> 64 k-tiles (all matrices)

// Scratch (static device globals — allocation-free per harness rules)
__device__ float    g_q   [(size_t)Bc * Tc * Cc];
__device__ float    g_k   [(size_t)Bc * Tc * Cc];   // fallback only
__device__ float    g_v   [(size_t)Bc * Tc * Cc];   // fallback only
__device__ uint32_t g_xp  [(size_t)(8192 / 128) * KT64 * TW];  // x  permuted
__device__ uint32_t g_wqp [(size_t)(6144 / 128) * KT64 * TW];  // Wqkv permuted
__device__ uint32_t g_wop [(size_t)(2048 / 128) * KT64 * TW];  // Wout permuted
__device__ uint32_t g_ypp [(size_t)(8192 / 128) * KT64 * TW];  // y permuted (from attn)

__device__ __forceinline__ uint32_t f2tf(float f) {
    uint32_t u;
    asm("cvt.rna.tf32.f32 %0, %1;" : "=r"(u) : "f"(f));
    return u;
}

__device__ __forceinline__ void cp16(uint32_t smem_dst, const void* gmem_src) {
    asm volatile("cp.async.cg.shared.global [%0], [%1], 16;\n"
                 :: "r"(smem_dst), "l"(gmem_src));
}
#define CP_COMMIT()  asm volatile("cp.async.commit_group;\n")
#define CP_WAIT(n)   asm volatile("cp.async.wait_group %0;\n" :: "n"(n))

#define MMA_TF32(d, a0, a1, a2, a3, b0, b1)                                   \
    asm volatile(                                                             \
        "mma.sync.aligned.m16n8k8.row.col.f32.tf32.tf32.f32 "                 \
        "{%0,%1,%2,%3}, {%4,%5,%6,%7}, {%8,%9}, {%0,%1,%2,%3};"               \
        : "+f"(d[0]), "+f"(d[1]), "+f"(d[2]), "+f"(d[3])                      \
        : "r"(a0), "r"(a1), "r"(a2), "r"(a3), "r"(b0), "r"(b1))

// ---------------------------------------------------------------------------
// Pre-pass: convert fp32 [rows x 2048] row-major -> permuted tf32 tile image.
// ---------------------------------------------------------------------------
__global__ __launch_bounds__(256)
void conv_perm(const float* __restrict__ src, uint32_t* __restrict__ dst)
{
    const int idx = blockIdx.x * 256 + threadIdx.x;   // float4 index
    const int e = idx << 2;
    const int r = e >> 11;
    const int k = e & 2047;
    float4 v = *(const float4*)(src + ((size_t)idx << 2));
    const int rt = r >> 7, rr = r & 127;
    const int kt = k >> 5, kk = k & 31;
    uint32_t* p = dst + ((size_t)(rt * KT64 + kt) * 128 + rr) * 36
                      + ((kk & 3) << 3) + (kk >> 2);
    p[0]  = f2tf(v.x);
    p[8]  = f2tf(v.y);
    p[16] = f2tf(v.z);
    p[24] = f2tf(v.w);
}

// ---------------------------------------------------------------------------
// TF32 tensor-core GEMM on pre-permuted operands, 3-stage cp.async pipeline.
// Block tile 128x128, 4 warps (2x2), warp tile 64x64.  (unchanged from R6)
// ---------------------------------------------------------------------------
static constexpr int GEMM_SMEM_BYTES = 6 * TW * 4;   // 110592

template <int MODE>
__global__ __launch_bounds__(128, 2)
void gemm_pp(const uint32_t* __restrict__ Ap, const uint32_t* __restrict__ Bp,
             const float* __restrict__ bias,
             float* __restrict__ outY, float* __restrict__ outQ,
             float* __restrict__ outK, float* __restrict__ outV, int N)
{
    extern __shared__ uint32_t dyn[];
    uint32_t* As = dyn;               // [3][4608]
    uint32_t* Bs = dyn + 3 * TW;      // [3][4608]

    const int tid  = threadIdx.x;
    const int lane = tid & 31;
    const int warp = tid >> 5;        // 0..3
    const int wm   = warp >> 1;
    const int wn   = warp & 1;
    const int m_off = wm * 64;
    const int n_off = wn * 64;
    const int grp = lane >> 2;
    const int tig = lane & 3;

    const uint32_t* At = Ap + (size_t)blockIdx.y * KT64 * TW;
    const uint32_t* Bt = Bp + (size_t)blockIdx.x * KT64 * TW;

    uint32_t sA, sB;
    {
        uint64_t a = __cvta_generic_to_shared(As);
        uint64_t b = __cvta_generic_to_shared(Bs);
        sA = (uint32_t)a; sB = (uint32_t)b;
    }

    auto issue = [&](int kt, int buf) {
        const uint32_t* ga = At + (size_t)kt * TW;
        const uint32_t* gb = Bt + (size_t)kt * TW;
        const uint32_t dA = sA + buf * (TW * 4);
        const uint32_t dB = sB + buf * (TW * 4);
#pragma unroll
        for (int i = 0; i < 18; i++) {
            int c = tid + i * 128;
            if (i < 9) cp16(dA + c * 16, ga + c * 4);
            else       cp16(dB + (c - 1152) * 16, gb + (c - 1152) * 4);
        }
    };

    float acc[4][8][4];
#pragma unroll
    for (int mi = 0; mi < 4; mi++)
#pragma unroll
        for (int ni = 0; ni < 8; ni++)
#pragma unroll
            for (int r = 0; r < 4; r++) acc[mi][ni][r] = 0.0f;

    issue(0, 0); CP_COMMIT();
    issue(1, 1); CP_COMMIT();

    for (int kt = 0; kt < KT64; kt++) {
        if (kt + 2 < KT64) issue(kt + 2, (kt + 2) % 3);
        CP_COMMIT();
        CP_WAIT(2);
        __syncthreads();

        const uint32_t* Ab = As + (kt % 3) * TW;
        const uint32_t* Bb = Bs + (kt % 3) * TW;
#pragma unroll
        for (int jp = 0; jp < 2; jp++) {
            uint4 af[4][2];
#pragma unroll
            for (int mi = 0; mi < 4; mi++) {
                int r0 = m_off + mi * 16 + grp;
                af[mi][0] = *(const uint4*)(Ab + r0 * 36 + tig * 8 + jp * 4);
                af[mi][1] = *(const uint4*)(Ab + (r0 + 8) * 36 + tig * 8 + jp * 4);
            }
#pragma unroll
            for (int nc = 0; nc < 2; nc++) {
                uint4 bf[4];
#pragma unroll
                for (int nj = 0; nj < 4; nj++) {
                    int col = n_off + (nc * 4 + nj) * 8 + grp;
                    bf[nj] = *(const uint4*)(Bb + col * 36 + tig * 8 + jp * 4);
                }
#pragma unroll
                for (int mi = 0; mi < 4; mi++)
#pragma unroll
                    for (int nj = 0; nj < 4; nj++) {
                        float* d = acc[mi][nc * 4 + nj];
                        MMA_TF32(d, af[mi][0].x, af[mi][1].x, af[mi][0].y, af[mi][1].y,
                                 bf[nj].x, bf[nj].y);
                        MMA_TF32(d, af[mi][0].z, af[mi][1].z, af[mi][0].w, af[mi][1].w,
                                 bf[nj].z, bf[nj].w);
                    }
            }
        }
        __syncthreads();
    }

#pragma unroll
    for (int mi = 0; mi < 4; mi++) {
#pragma unroll
        for (int s = 0; s < 2; s++) {
            const int gm = blockIdx.y * 128 + m_off + mi * 16 + grp + s * 8;
            const int bb = gm >> 11;
            const int t  = gm & 2047;
#pragma unroll
            for (int ni = 0; ni < 8; ni++) {
                const int gn = blockIdx.x * 128 + n_off + ni * 8 + tig * 2;
                float v0 = acc[mi][ni][s * 2 + 0] + bias[gn];
                float v1 = acc[mi][ni][s * 2 + 1] + bias[gn + 1];
                if (MODE == 0) {
                    const int sec = gn >> 11;
                    const int jj  = gn & 2047;
                    const int hh  = jj >> 7;
                    const int d   = jj & 127;
                    const size_t idx = (((size_t)bb * NH + hh) * Tc + t) * HD + d;
                    float* dst = (sec == 0) ? outQ : (sec == 1) ? outK : outV;
                    *(float2*)(dst + idx) = make_float2(v0, v1);
                } else {
                    *(float2*)(outY + (size_t)gm * N + gn) = make_float2(v0, v1);
                }
            }
        }
    }
}

// ---------------------------------------------------------------------------
// Tensor-core flash attention (causal), tf32 MMA, with REGISTER-PIPELINED
// K/V staging: tile j+1's GMEM loads are issued right after the barrier and
// consumed (convert+STS) at the top of iteration j+1, hiding LDG latency
// behind tile j's MMAs/softmax.
// ---------------------------------------------------------------------------
static constexpr int QCH = 128 * 36 + 8;
static constexpr int KCH = 64 * 36 + 8;
static constexpr int Q_WORDS  = 4 * QCH;
static constexpr int K_WORDS  = 4 * KCH;
static constexpr int VT_WORDS = 2 * QCH;
static constexpr int P_WORDS  = 128 * 68;
static constexpr int ATT_SMEM_BYTES = (Q_WORDS + K_WORDS + VT_WORDS + P_WORDS) * 4;

__global__ __launch_bounds__(256)
void attn_kernel(const float* __restrict__ Q, const float* __restrict__ K,
                 const float* __restrict__ V, uint32_t* __restrict__ Yp)
{
    extern __shared__ uint32_t smu[];
    uint32_t* q_s  = smu;
    uint32_t* k_s  = q_s + Q_WORDS;
    uint32_t* vt_s = k_s + K_WORDS;
    float*    p_s  = (float*)(vt_s + VT_WORDS);

    const int tid  = threadIdx.x;
    const int lane = tid & 31;
    const int w    = tid >> 5;
    const int grp  = lane >> 2;
    const int tig  = lane & 3;
    const int qb   = (int)gridDim.x - 1 - (int)blockIdx.x;
    const int h    = blockIdx.y;
    const int b    = blockIdx.z;

    const size_t bh = (((size_t)b * NH) + h) * Tc * HD;
    const float* Qb = Q + bh + (size_t)qb * 128 * HD;
    const float* Kb = K + bh;
    const float* Vb = V + bh;
    const float scale = 0.08838834764831845f;   // 1/sqrt(128)

#pragma unroll
    for (int i = 0; i < 16; i++) {
        int fl = tid + i * 256;
        int row = fl >> 5;
        int c4  = (fl & 31) << 2;
        float4 v4 = *(const float4*)(Qb + row * HD + c4);
        uint32_t* p = q_s + (c4 >> 5) * QCH + row * 36 + ((c4 & 31) >> 2);
        p[0]  = f2tf(v4.x * scale);
        p[8]  = f2tf(v4.y * scale);
        p[16] = f2tf(v4.z * scale);
        p[24] = f2tf(v4.w * scale);
    }

    float o[16][4];
#pragma unroll
    for (int nt = 0; nt < 16; nt++)
#pragma unroll
        for (int r = 0; r < 4; r++) o[nt][r] = 0.0f;
    float m0 = -1e30f, m1 = -1e30f, l0 = 0.0f, l1 = 0.0f;

    const int r0g = qb * 128 + 16 * w + grp;
    const int r1g = r0g + 8;
    const int pr0 = (16 * w + grp) * 68;
    const int pr1 = (16 * w + grp + 8) * 68;
    const int njt = 2 * qb + 2;

    // per-thread load coordinates (same mapping for K and V staging)
    int lrow[8], lc4[8];
#pragma unroll
    for (int i = 0; i < 8; i++) {
        int fl = tid + i * 256;
        lrow[i] = fl >> 5;
        lc4[i]  = (fl & 31) << 2;
    }

    // --- prologue: prefetch tile 0 into registers ---
    float4 kpre[8], vpre[8];
#pragma unroll
    for (int i = 0; i < 8; i++) {
        kpre[i] = *(const float4*)(Kb + lrow[i] * HD + lc4[i]);
        vpre[i] = *(const float4*)(Vb + lrow[i] * HD + lc4[i]);
    }

    for (int jb = 0; jb < njt; jb++) {
        __syncthreads();   // all warps done reading k_s/vt_s from tile jb-1
        // ---- convert + store tile jb from registers ----
#pragma unroll
        for (int i = 0; i < 8; i++) {
            uint32_t* p = k_s + (lc4[i] >> 5) * KCH + lrow[i] * 36 + ((lc4[i] & 31) >> 2);
            p[0]  = f2tf(kpre[i].x);
            p[8]  = f2tf(kpre[i].y);
            p[16] = f2tf(kpre[i].z);
            p[24] = f2tf(kpre[i].w);
        }
#pragma unroll
        for (int i = 0; i < 8; i++) {
            int kk = lrow[i] & 31;
            uint32_t* p = vt_s + (lrow[i] >> 5) * QCH + lc4[i] * 36 + (kk & 3) * 8 + (kk >> 2);
            p[0]   = f2tf(vpre[i].x);
            p[36]  = f2tf(vpre[i].y);
            p[72]  = f2tf(vpre[i].z);
            p[108] = f2tf(vpre[i].w);
        }
        __syncthreads();

        // ---- issue prefetch of tile jb+1 (latency hidden behind compute) ----
        if (jb + 1 < njt) {
            const float* Kn = Kb + (size_t)(jb + 1) * 64 * HD;
            const float* Vn = Vb + (size_t)(jb + 1) * 64 * HD;
#pragma unroll
            for (int i = 0; i < 8; i++) {
                kpre[i] = *(const float4*)(Kn + lrow[i] * HD + lc4[i]);
                vpre[i] = *(const float4*)(Vn + lrow[i] * HD + lc4[i]);
            }
        }

        // ---- S = Q * K^T  (warp: 16 x 64) ----
        float sacc[8][4];
#pragma unroll
        for (int nt = 0; nt < 8; nt++)
#pragma unroll
            for (int r = 0; r < 4; r++) sacc[nt][r] = 0.0f;

#pragma unroll
        for (int c = 0; c < 4; c++) {
#pragma unroll
            for (int jp = 0; jp < 2; jp++) {
                const uint32_t* qc = q_s + c * QCH + tig * 8 + jp * 4;
                uint4 a0 = *(const uint4*)(qc + (16 * w + grp) * 36);
                uint4 a1 = *(const uint4*)(qc + (16 * w + 8 + grp) * 36);
                const uint32_t* kc = k_s + c * KCH + tig * 8 + jp * 4;
#pragma unroll
                for (int nt = 0; nt < 8; nt++) {
                    uint4 bf = *(const uint4*)(kc + (nt * 8 + grp) * 36);
                    float* d = sacc[nt];
                    MMA_TF32(d, a0.x, a1.x, a0.y, a1.y, bf.x, bf.y);
                    MMA_TF32(d, a0.z, a1.z, a0.w, a1.w, bf.z, bf.w);
                }
            }
        }

        if (jb * 64 + 63 > qb * 128 + 16 * w) {
#pragma unroll
            for (int nt = 0; nt < 8; nt++) {
                int col = jb * 64 + nt * 8 + 2 * tig;
                if (col     > r0g) sacc[nt][0] = -1e30f;
                if (col + 1 > r0g) sacc[nt][1] = -1e30f;
                if (col     > r1g) sacc[nt][2] = -1e30f;
                if (col + 1 > r1g) sacc[nt][3] = -1e30f;
            }
        }

        float tm0 = -1e30f, tm1 = -1e30f;
#pragma unroll
        for (int nt = 0; nt < 8; nt++) {
            tm0 = fmaxf(tm0, fmaxf(sacc[nt][0], sacc[nt][1]));
            tm1 = fmaxf(tm1, fmaxf(sacc[nt][2], sacc[nt][3]));
        }
        tm0 = fmaxf(tm0, __shfl_xor_sync(0xffffffffu, tm0, 1));
        tm0 = fmaxf(tm0, __shfl_xor_sync(0xffffffffu, tm0, 2));
        tm1 = fmaxf(tm1, __shfl_xor_sync(0xffffffffu, tm1, 1));
        tm1 = fmaxf(tm1, __shfl_xor_sync(0xffffffffu, tm1, 2));
        float nm0 = fmaxf(m0, tm0), nm1 = fmaxf(m1, tm1);
        float al0 = __expf(m0 - nm0), al1 = __expf(m1 - nm1);
        m0 = nm0; m1 = nm1;

        float sum0 = 0.0f, sum1 = 0.0f;
#pragma unroll
        for (int nt = 0; nt < 8; nt++) {
            float p0 = __expf(sacc[nt][0] - m0);
            float p1 = __expf(sacc[nt][1] - m0);
            float p2 = __expf(sacc[nt][2] - m1);
            float p3 = __expf(sacc[nt][3] - m1);
            sum0 += p0 + p1;
            sum1 += p2 + p3;
            int cc = nt * 8 + 2 * tig;
            *(float2*)(p_s + pr0 + cc) = make_float2(p0, p1);
            *(float2*)(p_s + pr1 + cc) = make_float2(p2, p3);
        }
        sum0 += __shfl_xor_sync(0xffffffffu, sum0, 1);
        sum0 += __shfl_xor_sync(0xffffffffu, sum0, 2);
        sum1 += __shfl_xor_sync(0xffffffffu, sum1, 1);
        sum1 += __shfl_xor_sync(0xffffffffu, sum1, 2);
        l0 = l0 * al0 + sum0;
        l1 = l1 * al1 + sum1;

#pragma unroll
        for (int nt = 0; nt < 16; nt++) {
            o[nt][0] *= al0; o[nt][1] *= al0;
            o[nt][2] *= al1; o[nt][3] *= al1;
        }
        __syncwarp();

        // ---- O += P * V   (warp: 16 x 128, k = 64) ----
#pragma unroll
        for (int c = 0; c < 2; c++) {
#pragma unroll
            for (int jp = 0; jp < 2; jp++) {
                const int k0a = c * 32 + jp * 16;
                uint32_t ax0 = f2tf(p_s[pr0 + k0a + tig]);
                uint32_t ax1 = f2tf(p_s[pr1 + k0a + tig]);
                uint32_t ax2 = f2tf(p_s[pr0 + k0a + tig + 4]);
                uint32_t ax3 = f2tf(p_s[pr1 + k0a + tig + 4]);
                uint32_t az0 = f2tf(p_s[pr0 + k0a + 8 + tig]);
                uint32_t az1 = f2tf(p_s[pr1 + k0a + 8 + tig]);
                uint32_t az2 = f2tf(p_s[pr0 + k0a + 8 + tig + 4]);
                uint32_t az3 = f2tf(p_s[pr1 + k0a + 8 + tig + 4]);
                const uint32_t* vc = vt_s + c * QCH + tig * 8 + jp * 4;
#pragma unroll
                for (int nt = 0; nt < 16; nt++) {
                    uint4 bf = *(const uint4*)(vc + (nt * 8 + grp) * 36);
                    float* d = o[nt];
                    MMA_TF32(d, ax0, ax1, ax2, ax3, bf.x, bf.y);
                    MMA_TF32(d, az0, az1, az2, az3, bf.z, bf.w);
                }
            }
        }
    }

    // ---- normalize + write y straight into permuted tf32 image ----
    const float inv0 = 1.0f / l0;
    const float inv1 = 1.0f / l1;
    const int mt  = b * (Tc / 128) + qb;
    const int rr0 = 16 * w + grp;
    const int rr1 = rr0 + 8;
#pragma unroll
    for (int nt = 0; nt < 16; nt++) {
        const int colh = nt * 8 + 2 * tig;
        const int gn   = h * HD + colh;
        const int kt   = gn >> 5;
        const int kk   = gn & 31;
        const int pos  = ((kk & 3) << 3) + (kk >> 2);
        uint32_t* baseT = Yp + (size_t)(mt * KT64 + kt) * TW;
        baseT[rr0 * 36 + pos]     = f2tf(o[nt][0] * inv0);
        baseT[rr0 * 36 + pos + 8] = f2tf(o[nt][1] * inv0);
        baseT[rr1 * 36 + pos]     = f2tf(o[nt][2] * inv1);
        baseT[rr1 * 36 + pos + 8] = f2tf(o[nt][3] * inv1);
    }
}

// ---------------------------------------------------------------------------
// Launch
// ---------------------------------------------------------------------------
extern "C" void kernel_launch(void* const* d_in, const int* in_sizes, int n_in,
                              void* d_out, int out_size)
{
    const float* x    = (const float*)d_in[0];
    const float* Wqkv = (const float*)d_in[1];
    const float* bqkv = (const float*)d_in[2];
    const float* Wout = (const float*)d_in[3];
    const float* bout = (const float*)d_in[4];
    float* out = (float*)d_out;

    float *qp, *kp, *vp;
    uint32_t *xpp, *wqp, *wop, *ypp;
    cudaGetSymbolAddress((void**)&qp,  g_q);
    cudaGetSymbolAddress((void**)&xpp, g_xp);
    cudaGetSymbolAddress((void**)&wqp, g_wqp);
    cudaGetSymbolAddress((void**)&wop, g_wop);
    cudaGetSymbolAddress((void**)&ypp, g_ypp);
    if ((size_t)out_size >= 3 * YSZ) {
        kp = out + YSZ;          // new_k segment of output
        vp = out + 2 * YSZ;      // new_v segment of output
    } else {
        cudaGetSymbolAddress((void**)&kp, g_k);
        cudaGetSymbolAddress((void**)&vp, g_v);
    }

    cudaFuncSetAttribute(attn_kernel,
                         cudaFuncAttributeMaxDynamicSharedMemorySize,
                         ATT_SMEM_BYTES);
    cudaFuncSetAttribute(gemm_pp<0>,
                         cudaFuncAttributeMaxDynamicSharedMemorySize,
                         GEMM_SMEM_BYTES);
    cudaFuncSetAttribute(gemm_pp<1>,
                         cudaFuncAttributeMaxDynamicSharedMemorySize,
                         GEMM_SMEM_BYTES);

    // 0) Pre-permute x, Wqkv, Wout into tf32 tile images (DRAM-bound)
    conv_perm<<<8192 * 2, 256>>>(x,    xpp);
    conv_perm<<<6144 * 2, 256>>>(Wqkv, wqp);
    conv_perm<<<2048 * 2, 256>>>(Wout, wop);

    // 1) QKV projection: [8192, 6144] = x @ Wqkv^T + bqkv
    gemm_pp<0><<<dim3(6144 / 128, 8192 / 128), 128, GEMM_SMEM_BYTES>>>(
        xpp, wqp, bqkv, nullptr, qp, kp, vp, 3 * Cc);

    // 2) Causal attention (tf32 tensor cores, register-pipelined K/V staging)
    attn_kernel<<<dim3(Tc / 128, NH, Bc), 256, ATT_SMEM_BYTES>>>(qp, kp, vp, ypp);

    // 3) Output projection: [8192, 2048] = y @ Wout^T + bout
    gemm_pp<1><<<dim3(2048 / 128, 8192 / 128), 128, GEMM_SMEM_BYTES>>>(
        ypp, wop, bout, out, nullptr, nullptr, nullptr, Cc);
}

// round 16
// speedup vs baseline: 4.8180x; 1.3669x over previous
#include <cuda_runtime.h>
#include <cuda_fp16.h>
#include <cstdint>
#include <cstddef>

// Problem constants
static constexpr int Bc = 4;
static constexpr int Tc = 2048;
static constexpr int Cc = 2048;
static constexpr int NH = 16;
static constexpr int HD = 128;
static constexpr size_t YSZ = (size_t)Bc * Tc * Cc;   // 16777216

// fp16 pair-permuted tile geometry: [mtile][ktile][128 rows][20 words]
// row covers a k-tile of 32 elements = 16 half2 pairs; pair p at word
// pos(p) = (p&3)*4 + (p>>2); words 16..19 pad. Row stride 20 words = 80 B
// (16B-aligned => LDS.128 legal). Fragment load at word 4*tig reads pairs
// {tig, tig+4, tig+8, tig+12} = both m16n8k16 k-steps of the chunk.
// Bank check (8 rows/phase, stride 20): bases mod 32 = {0,20,8,28,16,4,24,12}
// all distinct -> conflict-free.
static constexpr int TWH  = 128 * 20;   // words per tile = 2560 (10240 B)
static constexpr int KT64 = 64;         // K = 2048 -> 64 k-tiles

// Scratch (static device globals)
__device__ float    g_q  [(size_t)Bc * Tc * Cc];
__device__ float    g_k  [(size_t)Bc * Tc * Cc];   // fallback only
__device__ float    g_v  [(size_t)Bc * Tc * Cc];   // fallback only
__device__ uint32_t g_xh [(size_t)64 * KT64 * TWH];  // x    fp16 image
__device__ uint32_t g_wqh[(size_t)48 * KT64 * TWH];  // Wqkv fp16 image
__device__ uint32_t g_woh[(size_t)16 * KT64 * TWH];  // Wout fp16 image
__device__ uint32_t g_yh [(size_t)64 * KT64 * TWH];  // y    fp16 image (attn out)

__device__ __forceinline__ uint32_t h2(float lo, float hi) {
    __half2 h = __floats2half2_rn(lo, hi);   // .x = lo (even k), .y = hi
    return *(uint32_t*)&h;
}
__device__ __forceinline__ int posf(int p) { return ((p & 3) << 2) | (p >> 2); }

__device__ __forceinline__ void cp16(uint32_t smem_dst, const void* gmem_src) {
    asm volatile("cp.async.cg.shared.global [%0], [%1], 16;\n"
                 :: "r"(smem_dst), "l"(gmem_src));
}
#define CP_COMMIT()  asm volatile("cp.async.commit_group;\n")
#define CP_WAIT(n)   asm volatile("cp.async.wait_group %0;\n" :: "n"(n))

#define MMA_F16(d, a0, a1, a2, a3, b0, b1)                                    \
    asm volatile(                                                             \
        "mma.sync.aligned.m16n8k16.row.col.f32.f16.f16.f32 "                  \
        "{%0,%1,%2,%3}, {%4,%5,%6,%7}, {%8,%9}, {%0,%1,%2,%3};"               \
        : "+f"(d[0]), "+f"(d[1]), "+f"(d[2]), "+f"(d[3])                      \
        : "r"(a0), "r"(a1), "r"(a2), "r"(a3), "r"(b0), "r"(b1))

// ---------------------------------------------------------------------------
// Pre-pass: fp32 [rows x 2048] row-major -> fp16 pair-permuted tile image.
// ---------------------------------------------------------------------------
__global__ __launch_bounds__(256)
void conv_h(const float* __restrict__ src, uint32_t* __restrict__ dst)
{
    const int idx = blockIdx.x * 256 + threadIdx.x;   // float4 index
    const int e = idx << 2;
    const int r = e >> 11;
    const int k = e & 2047;
    float4 v = *(const float4*)(src + ((size_t)idx << 2));
    const int rt = r >> 7, rr = r & 127;
    const int kt = k >> 5, kk = k & 31;               // kk multiple of 4
    const int p0 = kk >> 1;                           // even pair
    uint32_t* p = dst + (size_t)(rt * KT64 + kt) * TWH + rr * 20;
    p[posf(p0)]     = h2(v.x, v.y);
    p[posf(p0 + 1)] = h2(v.z, v.w);
}

// ---------------------------------------------------------------------------
// FP16 tensor-core GEMM (m16n8k16) on pre-permuted operands.
// Block tile 128x128, 4 warps (2x2), warp tile 64x64, BK=32.
// 3-stage cp.async ring, single barrier per k-tile.
// Per warp per k-tile: 16 LDS.128 feed 64 MMAs.
// ---------------------------------------------------------------------------
static constexpr int GEMM_SMEM_BYTES = 3 * 2 * TWH * 4;   // 61440

template <int MODE>
__global__ __launch_bounds__(128, 2)
void gemm_h(const uint32_t* __restrict__ Ap, const uint32_t* __restrict__ Bp,
            const float* __restrict__ bias,
            float* __restrict__ outY, float* __restrict__ outQ,
            float* __restrict__ outK, float* __restrict__ outV, int N)
{
    extern __shared__ uint32_t dyn[];   // [3][A 2560 ++ B 2560]

    const int tid  = threadIdx.x;
    const int lane = tid & 31;
    const int warp = tid >> 5;
    const int m_off = (warp >> 1) * 64;
    const int n_off = (warp & 1) * 64;
    const int grp = lane >> 2;
    const int tig = lane & 3;

    const uint32_t* At = Ap + (size_t)blockIdx.y * KT64 * TWH;
    const uint32_t* Bt = Bp + (size_t)blockIdx.x * KT64 * TWH;

    uint32_t sbase = (uint32_t)__cvta_generic_to_shared(dyn);

    auto issue = [&](int kt, int buf) {
        const uint32_t* ga = At + (size_t)kt * TWH;
        const uint32_t* gb = Bt + (size_t)kt * TWH;
        const uint32_t dA = sbase + buf * (2 * TWH * 4);
        const uint32_t dB = dA + TWH * 4;
#pragma unroll
        for (int i = 0; i < 5; i++) {               // 640 uint4 of A
            int c = tid + i * 128;
            cp16(dA + c * 16, ga + c * 4);
        }
#pragma unroll
        for (int i = 0; i < 5; i++) {               // 640 uint4 of B
            int c = tid + i * 128;
            cp16(dB + c * 16, gb + c * 4);
        }
    };

    float acc[4][8][4];
#pragma unroll
    for (int mi = 0; mi < 4; mi++)
#pragma unroll
        for (int ni = 0; ni < 8; ni++)
#pragma unroll
            for (int r = 0; r < 4; r++) acc[mi][ni][r] = 0.0f;

    issue(0, 0); CP_COMMIT();
    issue(1, 1); CP_COMMIT();

    for (int kt = 0; kt < KT64; kt++) {
        if (kt < KT64 - 1) { CP_WAIT(1); } else { CP_WAIT(0); }
        __syncthreads();                 // tile kt resident; stage (kt-1)%3 free
        if (kt + 2 < KT64) { issue(kt + 2, (kt + 2) % 3); CP_COMMIT(); }

        const uint32_t* Ab = dyn + (kt % 3) * (2 * TWH);
        const uint32_t* Bb = Ab + TWH;

        uint4 af[4][2];
#pragma unroll
        for (int mi = 0; mi < 4; mi++) {
            int r0 = m_off + mi * 16 + grp;
            af[mi][0] = *(const uint4*)(Ab + r0 * 20 + tig * 4);
            af[mi][1] = *(const uint4*)(Ab + (r0 + 8) * 20 + tig * 4);
        }
#pragma unroll
        for (int nc = 0; nc < 2; nc++) {
            uint4 bf[4];
#pragma unroll
            for (int nj = 0; nj < 4; nj++) {
                int col = n_off + (nc * 4 + nj) * 8 + grp;
                bf[nj] = *(const uint4*)(Bb + col * 20 + tig * 4);
            }
#pragma unroll
            for (int mi = 0; mi < 4; mi++)
#pragma unroll
                for (int nj = 0; nj < 4; nj++) {
                    float* d = acc[mi][nc * 4 + nj];
                    MMA_F16(d, af[mi][0].x, af[mi][1].x, af[mi][0].y, af[mi][1].y,
                            bf[nj].x, bf[nj].y);
                    MMA_F16(d, af[mi][0].z, af[mi][1].z, af[mi][0].w, af[mi][1].w,
                            bf[nj].z, bf[nj].w);
                }
        }
    }

    // Epilogue
#pragma unroll
    for (int mi = 0; mi < 4; mi++) {
#pragma unroll
        for (int s = 0; s < 2; s++) {
            const int gm = blockIdx.y * 128 + m_off + mi * 16 + grp + s * 8;
            const int bb = gm >> 11;
            const int t  = gm & 2047;
#pragma unroll
            for (int ni = 0; ni < 8; ni++) {
                const int gn = blockIdx.x * 128 + n_off + ni * 8 + tig * 2;
                float v0 = acc[mi][ni][s * 2 + 0] + bias[gn];
                float v1 = acc[mi][ni][s * 2 + 1] + bias[gn + 1];
                if (MODE == 0) {
                    const int sec = gn >> 11;
                    const int jj  = gn & 2047;
                    const int hh  = jj >> 7;
                    const int d   = jj & 127;
                    const size_t idx = (((size_t)bb * NH + hh) * Tc + t) * HD + d;
                    float* dst = (sec == 0) ? outQ : (sec == 1) ? outK : outV;
                    *(float2*)(dst + idx) = make_float2(v0, v1);
                } else {
                    *(float2*)(outY + (size_t)gm * N + gn) = make_float2(v0, v1);
                }
            }
        }
    }
}

// ---------------------------------------------------------------------------
// FP16 tensor-core flash attention (causal), register-pipelined K/V staging.
// Block: 128 Q rows x (h,b), 8 warps; warp owns 16 S/O rows.
// smem (u32): q_s[4][128*20+8], k_s[4][64*20+8], vt_s[2][128*20+8],
//             p_s[128][36] (half2 pairs; chunk c at word c*16; stride 36
//             => row base mod 32 in {0,4,...,28}: conflict-free uint4 loads).
// ---------------------------------------------------------------------------
static constexpr int QCHh = 128 * 20 + 8;   // 2568  (10272 B, 16B-aligned)
static constexpr int KCHh = 64 * 20 + 8;    // 1288  (5152 B, 16B-aligned)
static constexpr int Q_WORDS  = 4 * QCHh;   // 10272
static constexpr int K_WORDS  = 4 * KCHh;   // 5152
static constexpr int VT_WORDS = 2 * QCHh;   // 5136
static constexpr int P_WORDS  = 128 * 36;   // 4608
static constexpr int ATT_SMEM_BYTES = (Q_WORDS + K_WORDS + VT_WORDS + P_WORDS) * 4;

__global__ __launch_bounds__(256)
void attn_kernel(const float* __restrict__ Q, const float* __restrict__ K,
                 const float* __restrict__ V, uint32_t* __restrict__ Yp)
{
    extern __shared__ uint32_t smu[];
    uint32_t* q_s  = smu;
    uint32_t* k_s  = q_s + Q_WORDS;
    uint32_t* vt_s = k_s + K_WORDS;
    uint32_t* p_s  = vt_s + VT_WORDS;

    const int tid  = threadIdx.x;
    const int lane = tid & 31;
    const int w    = tid >> 5;
    const int grp  = lane >> 2;
    const int tig  = lane & 3;
    const int qb   = (int)gridDim.x - 1 - (int)blockIdx.x;
    const int h    = blockIdx.y;
    const int b    = blockIdx.z;

    const size_t bh = (((size_t)b * NH) + h) * Tc * HD;
    const float* Qb = Q + bh + (size_t)qb * 128 * HD;
    const float* Kb = K + bh;
    const float* Vb = V + bh;
    const float scale = 0.08838834764831845f;   // 1/sqrt(128)

    // Q tile (128x128) -> fp16 pair-permuted smem, pre-scaled
#pragma unroll
    for (int i = 0; i < 16; i++) {
        int fl = tid + i * 256;
        int row = fl >> 5;
        int c4  = (fl & 31) << 2;
        float4 v4 = *(const float4*)(Qb + row * HD + c4);
        int p0 = (c4 & 31) >> 1;
        uint32_t* p = q_s + (c4 >> 5) * QCHh + row * 20;
        p[posf(p0)]     = h2(v4.x * scale, v4.y * scale);
        p[posf(p0 + 1)] = h2(v4.z * scale, v4.w * scale);
    }

    float o[16][4];
#pragma unroll
    for (int nt = 0; nt < 16; nt++)
#pragma unroll
        for (int r = 0; r < 4; r++) o[nt][r] = 0.0f;
    float m0 = -1e30f, m1 = -1e30f, l0 = 0.0f, l1 = 0.0f;

    const int r0g = qb * 128 + 16 * w + grp;
    const int r1g = r0g + 8;
    const int pr0w = (16 * w + grp) * 36;
    const int pr1w = pr0w + 8 * 36;
    const int njt = 2 * qb + 2;

    int lrow[8], lc4[8];
#pragma unroll
    for (int i = 0; i < 8; i++) {
        int fl = tid + i * 256;
        lrow[i] = fl >> 5;
        lc4[i]  = (fl & 31) << 2;
    }

    float4 kpre[8], vpre[8];
#pragma unroll
    for (int i = 0; i < 8; i++) {
        kpre[i] = *(const float4*)(Kb + lrow[i] * HD + lc4[i]);
        vpre[i] = *(const float4*)(Vb + lrow[i] * HD + lc4[i]);
    }

    for (int jb = 0; jb < njt; jb++) {
        __syncthreads();
        // K tile jb: fp16 pair-permuted
#pragma unroll
        for (int i = 0; i < 8; i++) {
            int p0 = (lc4[i] & 31) >> 1;
            uint32_t* p = k_s + (lc4[i] >> 5) * KCHh + lrow[i] * 20;
            p[posf(p0)]     = h2(kpre[i].x, kpre[i].y);
            p[posf(p0 + 1)] = h2(kpre[i].z, kpre[i].w);
        }
        // V tile jb: TRANSPOSED fp16 (n rows, k pairs); half-granular stores
#pragma unroll
        for (int i = 0; i < 8; i++) {
            int kr = lrow[i];
            int pk = (kr & 31) >> 1;
            int hsel = (kr & 1) << 1;            // byte offset within half2
            char* base = (char*)(vt_s + (kr >> 5) * QCHh) + posf(pk) * 4 + hsel;
            *(__half*)(base + (lc4[i] + 0) * 80) = __float2half_rn(vpre[i].x);
            *(__half*)(base + (lc4[i] + 1) * 80) = __float2half_rn(vpre[i].y);
            *(__half*)(base + (lc4[i] + 2) * 80) = __float2half_rn(vpre[i].z);
            *(__half*)(base + (lc4[i] + 3) * 80) = __float2half_rn(vpre[i].w);
        }
        __syncthreads();

        if (jb + 1 < njt) {
            const float* Kn = Kb + (size_t)(jb + 1) * 64 * HD;
            const float* Vn = Vb + (size_t)(jb + 1) * 64 * HD;
#pragma unroll
            for (int i = 0; i < 8; i++) {
                kpre[i] = *(const float4*)(Kn + lrow[i] * HD + lc4[i]);
                vpre[i] = *(const float4*)(Vn + lrow[i] * HD + lc4[i]);
            }
        }

        // ---- S = Q * K^T  (warp 16x64, K=128: 4 chunks x 2 k16-steps) ----
        float sacc[8][4];
#pragma unroll
        for (int nt = 0; nt < 8; nt++)
#pragma unroll
            for (int r = 0; r < 4; r++) sacc[nt][r] = 0.0f;

#pragma unroll
        for (int c = 0; c < 4; c++) {
            const uint32_t* qc = q_s + c * QCHh + tig * 4;
            uint4 a0 = *(const uint4*)(qc + (16 * w + grp) * 20);
            uint4 a1 = *(const uint4*)(qc + (16 * w + 8 + grp) * 20);
            const uint32_t* kc = k_s + c * KCHh + tig * 4;
#pragma unroll
            for (int nt = 0; nt < 8; nt++) {
                uint4 bf = *(const uint4*)(kc + (nt * 8 + grp) * 20);
                float* d = sacc[nt];
                MMA_F16(d, a0.x, a1.x, a0.y, a1.y, bf.x, bf.y);
                MMA_F16(d, a0.z, a1.z, a0.w, a1.w, bf.z, bf.w);
            }
        }

        if (jb * 64 + 63 > qb * 128 + 16 * w) {
#pragma unroll
            for (int nt = 0; nt < 8; nt++) {
                int col = jb * 64 + nt * 8 + 2 * tig;
                if (col     > r0g) sacc[nt][0] = -1e30f;
                if (col + 1 > r0g) sacc[nt][1] = -1e30f;
                if (col     > r1g) sacc[nt][2] = -1e30f;
                if (col + 1 > r1g) sacc[nt][3] = -1e30f;
            }
        }

        float tm0 = -1e30f, tm1 = -1e30f;
#pragma unroll
        for (int nt = 0; nt < 8; nt++) {
            tm0 = fmaxf(tm0, fmaxf(sacc[nt][0], sacc[nt][1]));
            tm1 = fmaxf(tm1, fmaxf(sacc[nt][2], sacc[nt][3]));
        }
        tm0 = fmaxf(tm0, __shfl_xor_sync(0xffffffffu, tm0, 1));
        tm0 = fmaxf(tm0, __shfl_xor_sync(0xffffffffu, tm0, 2));
        tm1 = fmaxf(tm1, __shfl_xor_sync(0xffffffffu, tm1, 1));
        tm1 = fmaxf(tm1, __shfl_xor_sync(0xffffffffu, tm1, 2));
        float nm0 = fmaxf(m0, tm0), nm1 = fmaxf(m1, tm1);
        float al0 = __expf(m0 - nm0), al1 = __expf(m1 - nm1);
        m0 = nm0; m1 = nm1;

        float sum0 = 0.0f, sum1 = 0.0f;
#pragma unroll
        for (int nt = 0; nt < 8; nt++) {
            float p0 = __expf(sacc[nt][0] - m0);
            float p1 = __expf(sacc[nt][1] - m0);
            float p2 = __expf(sacc[nt][2] - m1);
            float p3 = __expf(sacc[nt][3] - m1);
            sum0 += p0 + p1;
            sum1 += p2 + p3;
            int pidx = nt * 4 + tig;
            int off  = (pidx >> 4) * 16 + posf(pidx & 15);
            p_s[pr0w + off] = h2(p0, p1);
            p_s[pr1w + off] = h2(p2, p3);
        }
        sum0 += __shfl_xor_sync(0xffffffffu, sum0, 1);
        sum0 += __shfl_xor_sync(0xffffffffu, sum0, 2);
        sum1 += __shfl_xor_sync(0xffffffffu, sum1, 1);
        sum1 += __shfl_xor_sync(0xffffffffu, sum1, 2);
        l0 = l0 * al0 + sum0;
        l1 = l1 * al1 + sum1;

#pragma unroll
        for (int nt = 0; nt < 16; nt++) {
            o[nt][0] *= al0; o[nt][1] *= al0;
            o[nt][2] *= al1; o[nt][3] *= al1;
        }
        __syncwarp();

        // ---- O += P * V   (warp 16x128, k=64: 2 chunks x 2 k16-steps) ----
#pragma unroll
        for (int c = 0; c < 2; c++) {
            uint4 pa0 = *(const uint4*)(p_s + pr0w + c * 16 + tig * 4);
            uint4 pa1 = *(const uint4*)(p_s + pr1w + c * 16 + tig * 4);
            const uint32_t* vc = vt_s + c * QCHh + tig * 4;
#pragma unroll
            for (int nt = 0; nt < 16; nt++) {
                uint4 bf = *(const uint4*)(vc + (nt * 8 + grp) * 20);
                float* d = o[nt];
                MMA_F16(d, pa0.x, pa1.x, pa0.y, pa1.y, bf.x, bf.y);
                MMA_F16(d, pa0.z, pa1.z, pa0.w, pa1.w, bf.z, bf.w);
            }
        }
    }

    // ---- normalize + write y into fp16 pair-permuted image ----
    const float inv0 = 1.0f / l0;
    const float inv1 = 1.0f / l1;
    const int mt  = b * (Tc / 128) + qb;
    const int rr0 = 16 * w + grp;
    const int rr1 = rr0 + 8;
#pragma unroll
    for (int nt = 0; nt < 16; nt++) {
        const int gp = (h * HD + nt * 8 + 2 * tig) >> 1;   // global pair index
        const int kt = gp >> 4;
        const int pc = gp & 15;
        uint32_t* baseT = Yp + (size_t)(mt * KT64 + kt) * TWH;
        baseT[rr0 * 20 + posf(pc)] = h2(o[nt][0] * inv0, o[nt][1] * inv0);
        baseT[rr1 * 20 + posf(pc)] = h2(o[nt][2] * inv1, o[nt][3] * inv1);
    }
}

// ---------------------------------------------------------------------------
// Launch
// ---------------------------------------------------------------------------
extern "C" void kernel_launch(void* const* d_in, const int* in_sizes, int n_in,
                              void* d_out, int out_size)
{
    const float* x    = (const float*)d_in[0];
    const float* Wqkv = (const float*)d_in[1];
    const float* bqkv = (const float*)d_in[2];
    const float* Wout = (const float*)d_in[3];
    const float* bout = (const float*)d_in[4];
    float* out = (float*)d_out;

    float *qp, *kp, *vp;
    uint32_t *xh, *wqh, *woh, *yh;
    cudaGetSymbolAddress((void**)&qp,  g_q);
    cudaGetSymbolAddress((void**)&xh,  g_xh);
    cudaGetSymbolAddress((void**)&wqh, g_wqh);
    cudaGetSymbolAddress((void**)&woh, g_woh);
    cudaGetSymbolAddress((void**)&yh,  g_yh);
    if ((size_t)out_size >= 3 * YSZ) {
        kp = out + YSZ;
        vp = out + 2 * YSZ;
    } else {
        cudaGetSymbolAddress((void**)&kp, g_k);
        cudaGetSymbolAddress((void**)&vp, g_v);
    }

    cudaFuncSetAttribute(attn_kernel,
                         cudaFuncAttributeMaxDynamicSharedMemorySize,
                         ATT_SMEM_BYTES);
    cudaFuncSetAttribute(gemm_h<0>,
                         cudaFuncAttributeMaxDynamicSharedMemorySize,
                         GEMM_SMEM_BYTES);
    cudaFuncSetAttribute(gemm_h<1>,
                         cudaFuncAttributeMaxDynamicSharedMemorySize,
                         GEMM_SMEM_BYTES);

    // 0) Pre-pass: fp16 pair-permuted images
    conv_h<<<8192 * 2, 256>>>(x,    xh);
    conv_h<<<6144 * 2, 256>>>(Wqkv, wqh);
    conv_h<<<2048 * 2, 256>>>(Wout, woh);

    // 1) QKV projection: [8192, 6144] = x @ Wqkv^T + bqkv  (fp16 m16n8k16)
    gemm_h<0><<<dim3(6144 / 128, 8192 / 128), 128, GEMM_SMEM_BYTES>>>(
        xh, wqh, bqkv, nullptr, qp, kp, vp, 3 * Cc);

    // 2) Causal attention (fp16 tensor cores); y -> fp16 image g_yh
    attn_kernel<<<dim3(Tc / 128, NH, Bc), 256, ATT_SMEM_BYTES>>>(qp, kp, vp, yh);

    // 3) Output projection: [8192, 2048] = y @ Wout^T + bout
    gemm_h<1><<<dim3(2048 / 128, 8192 / 128), 128, GEMM_SMEM_BYTES>>>(
        yh, woh, bout, out, nullptr, nullptr, nullptr, Cc);
}